// round 1
// baseline (speedup 1.0000x reference)
#include <cuda_runtime.h>
#include <math.h>

#define NROWS 8192
#define DIM   128
#define BHALF 4096      // B (batch size); pos pairs are j = i +/- BHALF
#define BT    128       // tile edge
#define NT    (NROWS / BT)   // 64 tiles per dim
#define POS_TILE_DELTA (BHALF / BT)  // 32

// Global scratch (no allocations allowed)
__device__ double g_S1, g_S2, g_POS;
__device__ double g_rowsum[NROWS];
__device__ float  g_norm[NROWS];

__global__ void init_kernel() {
    int t = blockIdx.x * blockDim.x + threadIdx.x;
    if (t < NROWS) g_rowsum[t] = 0.0;
    if (t == 0) { g_S1 = 0.0; g_S2 = 0.0; g_POS = 0.0; }
}

// one warp per row: n_i = sum_k x_ik^2
__global__ void norm_kernel(const float* __restrict__ feat) {
    int gw = (blockIdx.x * blockDim.x + threadIdx.x) >> 5;
    int lane = threadIdx.x & 31;
    if (gw >= NROWS) return;
    const float* r = feat + gw * DIM;
    float s = 0.f;
#pragma unroll
    for (int k = 0; k < DIM / 32; ++k) {
        float v = r[lane + 32 * k];
        s = fmaf(v, v, s);
    }
#pragma unroll
    for (int o = 16; o; o >>= 1) s += __shfl_xor_sync(0xffffffffu, s, o);
    if (lane == 0) g_norm[gw] = s;
}

// Fused tile kernel: 128x128 output tile per CTA, upper triangle only.
// smem: A tile + B tile, stored TRANSPOSED (sX[k*BT + mn]) for conflict-free
// float4 fragment loads in the k-loop.
__global__ __launch_bounds__(256, 1)
void tile_kernel(const float* __restrict__ feat) {
    const int I = blockIdx.y;
    const int J = blockIdx.x;
    if (J < I) return;                      // symmetry: upper triangle only
    const bool diagT = (I == J);
    const bool posT  = (J == I + POS_TILE_DELTA);

    extern __shared__ float smem[];
    float* sA = smem;
    float* sB = diagT ? sA : (smem + DIM * BT);

    const int t  = threadIdx.x;
    const int tx = t & 15;
    const int ty = t >> 4;
    const int r0 = ty * 8;
    const int c0 = tx * 8;

    __shared__ float redRow[BT];
    __shared__ float redCol[BT];
    __shared__ float redS[3];
    if (t < BT) { redRow[t] = 0.f; redCol[t] = 0.f; }
    if (t < 3)  redS[t] = 0.f;

    // ---- load tiles (coalesced float4 reads, transposed scalar smem stores)
    {
        const float* gA = feat + (size_t)I * BT * DIM;
#pragma unroll
        for (int c = 0; c < 16; ++c) {
            int idx = c * 256 + t;          // float4 index
            int row = idx >> 5;             // 32 float4 per row
            int k4  = idx & 31;
            float4 v = *reinterpret_cast<const float4*>(gA + row * DIM + k4 * 4);
            sA[(k4 * 4 + 0) * BT + row] = v.x;
            sA[(k4 * 4 + 1) * BT + row] = v.y;
            sA[(k4 * 4 + 2) * BT + row] = v.z;
            sA[(k4 * 4 + 3) * BT + row] = v.w;
        }
        if (!diagT) {
            const float* gB = feat + (size_t)J * BT * DIM;
#pragma unroll
            for (int c = 0; c < 16; ++c) {
                int idx = c * 256 + t;
                int row = idx >> 5;
                int k4  = idx & 31;
                float4 v = *reinterpret_cast<const float4*>(gB + row * DIM + k4 * 4);
                sB[(k4 * 4 + 0) * BT + row] = v.x;
                sB[(k4 * 4 + 1) * BT + row] = v.y;
                sB[(k4 * 4 + 2) * BT + row] = v.z;
                sB[(k4 * 4 + 3) * BT + row] = v.w;
            }
        }
    }
    __syncthreads();

    // ---- 8x8 register-blocked fp32 GEMM over full D=128
    float acc[8][8];
#pragma unroll
    for (int m = 0; m < 8; ++m)
#pragma unroll
        for (int n = 0; n < 8; ++n) acc[m][n] = 0.f;

#pragma unroll 2
    for (int k = 0; k < DIM; ++k) {
        float4 a0 = *reinterpret_cast<const float4*>(sA + k * BT + r0);
        float4 a1 = *reinterpret_cast<const float4*>(sA + k * BT + r0 + 4);
        float4 b0 = *reinterpret_cast<const float4*>(sB + k * BT + c0);
        float4 b1 = *reinterpret_cast<const float4*>(sB + k * BT + c0 + 4);
        float ar[8] = {a0.x, a0.y, a0.z, a0.w, a1.x, a1.y, a1.z, a1.w};
        float bc[8] = {b0.x, b0.y, b0.z, b0.w, b1.x, b1.y, b1.z, b1.w};
#pragma unroll
        for (int m = 0; m < 8; ++m)
#pragma unroll
            for (int n = 0; n < 8; ++n)
                acc[m][n] = fmaf(ar[m], bc[n], acc[m][n]);
    }

    // ---- fused epilogue: K = exp(-sq/2), accumulate S1, S2, pos, row/col sums
    float nI[8], nJ[8];
#pragma unroll
    for (int m = 0; m < 8; ++m) nI[m] = g_norm[I * BT + r0 + m];
#pragma unroll
    for (int n = 0; n < 8; ++n) nJ[n] = g_norm[J * BT + c0 + n];

    float s1 = 0.f, s2 = 0.f, pos = 0.f;
    float rp[8], cp[8];
#pragma unroll
    for (int m = 0; m < 8; ++m) rp[m] = 0.f;
#pragma unroll
    for (int n = 0; n < 8; ++n) cp[n] = 0.f;

#pragma unroll
    for (int m = 0; m < 8; ++m) {
#pragma unroll
        for (int n = 0; n < 8; ++n) {
            float sq = nI[m] + nJ[n] - 2.f * acc[m][n];
            sq = fmaxf(sq, 0.f);
            float e = __expf(-0.5f * sq);
            bool localDiag = (r0 + m) == (c0 + n);
            if (diagT && localDiag) e = 1.0f;     // exact K_ii
            if (posT && localDiag) pos += e;      // j - i == BHALF elements
            s1 += e;
            s2 = fmaf(e, e, s2);
            rp[m] += e;
            cp[n] += e;
        }
    }

    // row partials: reduce over tx (lanes share the same 16-group in a warp)
#pragma unroll
    for (int m = 0; m < 8; ++m) {
        float v = rp[m];
#pragma unroll
        for (int o = 8; o; o >>= 1) v += __shfl_xor_sync(0xffffffffu, v, o);
        if (tx == 0) redRow[r0 + m] = v;          // unique (ty,m) per row
    }
    // col partials: smem atomics (2-way address sharing per warp only)
#pragma unroll
    for (int n = 0; n < 8; ++n) atomicAdd(&redCol[c0 + n], cp[n]);

    // scalar partials: full-warp reduce then one smem atomic per warp
#pragma unroll
    for (int o = 16; o; o >>= 1) {
        s1  += __shfl_xor_sync(0xffffffffu, s1, o);
        s2  += __shfl_xor_sync(0xffffffffu, s2, o);
        pos += __shfl_xor_sync(0xffffffffu, pos, o);
    }
    if ((t & 31) == 0) {
        atomicAdd(&redS[0], s1);
        atomicAdd(&redS[1], s2);
        atomicAdd(&redS[2], pos);
    }
    __syncthreads();

    const double w = diagT ? 1.0 : 2.0;           // symmetry weight
    if (t == 0) {
        atomicAdd(&g_S1, w * (double)redS[0]);
        atomicAdd(&g_S2, w * (double)redS[1]);
        if (posT) atomicAdd(&g_POS, 2.0 * (double)redS[2]);
    }
    if (t < BT) {
        atomicAdd(&g_rowsum[I * BT + t], (double)redRow[t]);
        if (!diagT) atomicAdd(&g_rowsum[J * BT + t], (double)redCol[t]);
    }
}

__global__ void final_kernel(float* out) {
    __shared__ double sh[256];
    int t = threadIdx.x;
    double sr2 = 0.0;
    for (int i = t; i < NROWS; i += 256) {
        double r = g_rowsum[i];
        sr2 += r * r;
    }
    sh[t] = sr2;
    __syncthreads();
    for (int s = 128; s; s >>= 1) {
        if (t < s) sh[t] += sh[t + s];
        __syncthreads();
    }
    if (t == 0) {
        const double Nd = (double)NROWS;
        const double Bd = (double)BHALF;
        double S1  = g_S1;
        double S2  = g_S2;
        double POS = g_POS;
        double SR2 = sh[0];

        double trace = Nd;                       // K_ii == 1 exactly
        double neg   = S1 - trace - POS;
        double term1 = POS / (Bd * 2.0);         // B*M*(M-1), M=2
        double term2 = neg / (Bd * Bd * 4.0);    // B^2*M^2
        double scale = Bd / (Bd - 1.0);
        double hsic_zy = scale * (term1 - term2 - 1.0);

        // mean(Kc^2) = (S2 - 2*SR2/N + (S1/N)^2) / N^2   (exact identity)
        double hsic_zz = (S2 - 2.0 * SR2 / Nd + (S1 / Nd) * (S1 / Nd)) / (Nd * Nd);
        if (hsic_zz < 0.0) hsic_zz = 0.0;

        out[0] = (float)(-hsic_zy + 3.0 * sqrt(hsic_zz));
    }
}

extern "C" void kernel_launch(void* const* d_in, const int* in_sizes, int n_in,
                              void* d_out, int out_size) {
    const float* feat = (const float*)d_in[0];
    float* out = (float*)d_out;

    cudaFuncSetAttribute(tile_kernel,
                         cudaFuncAttributeMaxDynamicSharedMemorySize,
                         2 * BT * DIM * (int)sizeof(float));

    init_kernel<<<(NROWS + 255) / 256, 256>>>();
    norm_kernel<<<(NROWS * 32 + 255) / 256, 256>>>(feat);
    dim3 grid(NT, NT);
    tile_kernel<<<grid, 256, 2 * BT * DIM * sizeof(float)>>>(feat);
    final_kernel<<<1, 256>>>(out);
}

// round 3
// speedup vs baseline: 6.6565x; 6.6565x over previous
#include <cuda_runtime.h>
#include <cuda_bf16.h>
#include <math.h>
#include <stdint.h>

#define NROWS 8192
#define DIM   128
#define BHALF 4096
#define BT    128
#define NT    (NROWS / BT)          // 64
#define POS_DELTA (BHALF / BT)      // 32

// ---------------- global scratch (no allocations allowed) ----------------
__device__ double g_S1, g_S2, g_POS;
__device__ double g_rowsum[NROWS];
__device__ float  g_h[NROWS];                           // 0.5 * ||x_i||^2 (fp32)
__device__ __align__(16) uint4 g_bf16[NROWS * 16];      // pre-swizzled bf16 rows (256B/row)

// ---------------- setup kernels ----------------
__global__ void init_kernel() {
    int t = blockIdx.x * blockDim.x + threadIdx.x;
    if (t < NROWS) g_rowsum[t] = 0.0;
    if (t == 0) { g_S1 = 0.0; g_S2 = 0.0; g_POS = 0.0; }
}

// one warp per row: g_h[i] = 0.5 * sum_k x_ik^2 (fp32, exact inputs)
__global__ void norm_kernel(const float* __restrict__ feat) {
    int gw = (blockIdx.x * blockDim.x + threadIdx.x) >> 5;
    int lane = threadIdx.x & 31;
    if (gw >= NROWS) return;
    const float* r = feat + gw * DIM;
    float s = 0.f;
#pragma unroll
    for (int k = 0; k < DIM / 32; ++k) { float v = r[lane + 32 * k]; s = fmaf(v, v, s); }
#pragma unroll
    for (int o = 16; o; o >>= 1) s += __shfl_xor_sync(0xffffffffu, s, o);
    if (lane == 0) g_h[gw] = 0.5f * s;
}

// fp32 -> bf16, stored with a per-row XOR swizzle at 16B granularity:
// uint4 index = row*16 + (chunk ^ (row & 7)),  chunk = k/8.
// Tile kernels then copy 16B words verbatim and ldmatrix reads are conflict-free.
__global__ void convert_kernel(const float* __restrict__ feat) {
    int t = blockIdx.x * blockDim.x + threadIdx.x;   // one uint4 (8 bf16) per thread
    int row = t >> 4;
    int chunk = t & 15;
    const float4* src = reinterpret_cast<const float4*>(feat + row * DIM + chunk * 8);
    float4 a = src[0], b = src[1];
    __nv_bfloat162 p0 = __floats2bfloat162_rn(a.x, a.y);
    __nv_bfloat162 p1 = __floats2bfloat162_rn(a.z, a.w);
    __nv_bfloat162 p2 = __floats2bfloat162_rn(b.x, b.y);
    __nv_bfloat162 p3 = __floats2bfloat162_rn(b.z, b.w);
    uint4 v;
    v.x = *reinterpret_cast<uint32_t*>(&p0);
    v.y = *reinterpret_cast<uint32_t*>(&p1);
    v.z = *reinterpret_cast<uint32_t*>(&p2);
    v.w = *reinterpret_cast<uint32_t*>(&p3);
    g_bf16[row * 16 + (chunk ^ (row & 7))] = v;
}

// ---------------- helpers ----------------
__device__ __forceinline__ uint32_t smem_u32(const void* p) {
    uint32_t a;
    asm("{ .reg .u64 t; cvta.to.shared.u64 t, %1; cvt.u32.u64 %0, t; }" : "=r"(a) : "l"(p));
    return a;
}
__device__ __forceinline__ void ldmatrix_x4(uint32_t& r0, uint32_t& r1, uint32_t& r2,
                                            uint32_t& r3, uint32_t addr) {
    asm volatile("ldmatrix.sync.aligned.m8n8.x4.shared.b16 {%0,%1,%2,%3}, [%4];"
                 : "=r"(r0), "=r"(r1), "=r"(r2), "=r"(r3) : "r"(addr));
}
__device__ __forceinline__ void mma_bf16(float& c0, float& c1, float& c2, float& c3,
                                         uint32_t a0, uint32_t a1, uint32_t a2, uint32_t a3,
                                         uint32_t b0, uint32_t b1) {
    asm volatile("mma.sync.aligned.m16n8k16.row.col.f32.bf16.bf16.f32 "
                 "{%0,%1,%2,%3}, {%4,%5,%6,%7}, {%8,%9}, {%0,%1,%2,%3};"
                 : "+f"(c0), "+f"(c1), "+f"(c2), "+f"(c3)
                 : "r"(a0), "r"(a1), "r"(a2), "r"(a3), "r"(b0), "r"(b1));
}

// ---------------- fused tile kernel ----------------
// One CTA (256 thr, 8 warps) = one 128x128 tile of K, upper triangle only.
// Warp grid 4(m) x 2(n); each warp computes 32x64 via 2x8 m16n8k16 fragments.
__global__ __launch_bounds__(256, 2)
void tile_kernel() {
    const int I = blockIdx.y;
    const int J = blockIdx.x;
    if (J < I) return;
    const bool diagT = (I == J);
    const bool posT  = (J == I + POS_DELTA);

    extern __shared__ unsigned char smem[];
    uint4* sA4 = reinterpret_cast<uint4*>(smem);              // 32KB
    uint4* sB4 = reinterpret_cast<uint4*>(smem + 32768);      // 32KB
    float* redRow = reinterpret_cast<float*>(smem + 65536);   // [128]
    float* redCol = reinterpret_cast<float*>(smem + 66048);   // [128]
    float* sHI    = reinterpret_cast<float*>(smem + 66560);   // [128]
    float* sHJ    = reinterpret_cast<float*>(smem + 67072);   // [128]
    float* redS   = reinterpret_cast<float*>(smem + 67584);   // [3]

    const int t = threadIdx.x, wid = t >> 5, lane = t & 31;
    const int warp_m = wid & 3, warp_n = wid >> 2;

    // tile loads: verbatim 16B copies of the pre-swizzled image
    {
        const uint4* srcA = g_bf16 + I * 2048;
#pragma unroll
        for (int i = 0; i < 8; ++i) sA4[i * 256 + t] = srcA[i * 256 + t];
        if (!diagT) {
            const uint4* srcB = g_bf16 + J * 2048;
#pragma unroll
            for (int i = 0; i < 8; ++i) sB4[i * 256 + t] = srcB[i * 256 + t];
        }
    }
    if (t < 128) { redRow[t] = 0.f; sHI[t] = g_h[I * BT + t]; }
    else         { redCol[t - 128] = 0.f; sHJ[t - 128] = g_h[J * BT + t - 128]; }
    if (t < 3) redS[t] = 0.f;
    __syncthreads();

    const uint32_t sAa = smem_u32(sA4);
    const uint32_t sBa = diagT ? sAa : smem_u32(sB4);

    // per-lane ldmatrix address precompute
    // A: row = warp_m*32 + mi*16 + (lane&15), k-sub = lane>>4
    const int aRow0 = warp_m * 32 + (lane & 15);
    const int aSub  = lane >> 4;
    // B pair p: n = warp_n*64 + p*16 + (lane&7) + ((lane>>4)<<3), k-sub = (lane>>3)&1
    const int bRowB = warp_n * 64 + (lane & 7) + ((lane >> 4) << 3);
    const int bSub  = (lane >> 3) & 1;

    float acc[2][8][4];
#pragma unroll
    for (int mi = 0; mi < 2; ++mi)
#pragma unroll
        for (int ni = 0; ni < 8; ++ni)
#pragma unroll
            for (int k = 0; k < 4; ++k) acc[mi][ni][k] = 0.f;

#pragma unroll
    for (int kc = 0; kc < 8; ++kc) {
        uint32_t a[2][4];
#pragma unroll
        for (int mi = 0; mi < 2; ++mi) {
            int row = aRow0 + mi * 16;
            uint32_t addr = sAa + row * 256 + (((2 * kc + aSub) ^ (row & 7)) << 4);
            ldmatrix_x4(a[mi][0], a[mi][1], a[mi][2], a[mi][3], addr);
        }
        uint32_t b[8][2];
#pragma unroll
        for (int p = 0; p < 4; ++p) {
            int row = bRowB + p * 16;
            uint32_t addr = sBa + row * 256 + (((2 * kc + bSub) ^ (row & 7)) << 4);
            uint32_t r0, r1, r2, r3;
            ldmatrix_x4(r0, r1, r2, r3, addr);
            b[2 * p][0] = r0; b[2 * p][1] = r1;
            b[2 * p + 1][0] = r2; b[2 * p + 1][1] = r3;
        }
#pragma unroll
        for (int mi = 0; mi < 2; ++mi)
#pragma unroll
            for (int ni = 0; ni < 8; ++ni)
                mma_bf16(acc[mi][ni][0], acc[mi][ni][1], acc[mi][ni][2], acc[mi][ni][3],
                         a[mi][0], a[mi][1], a[mi][2], a[mi][3], b[ni][0], b[ni][1]);
    }

    // ---- fused epilogue: e = min(exp(dot - hI - hJ), 1); reduce all stats
    const int groupID = lane >> 2, qp = lane & 3;
    float s1 = 0.f, s2 = 0.f, pos = 0.f;
    float rAcc[2][2] = {{0.f, 0.f}, {0.f, 0.f}};
    float cAcc[8][2];
#pragma unroll
    for (int ni = 0; ni < 8; ++ni) { cAcc[ni][0] = 0.f; cAcc[ni][1] = 0.f; }

#pragma unroll
    for (int mi = 0; mi < 2; ++mi) {
        const int r0 = warp_m * 32 + mi * 16 + groupID;   // tile-local rows
        const int r1 = r0 + 8;
        const float hI0 = sHI[r0], hI1 = sHI[r1];
#pragma unroll
        for (int ni = 0; ni < 8; ++ni) {
            const int c0 = warp_n * 64 + ni * 8 + 2 * qp; // tile-local cols
            const int c1 = c0 + 1;
            const float hJ0 = sHJ[c0], hJ1 = sHJ[c1];
            float e00 = fminf(__expf(acc[mi][ni][0] - hI0 - hJ0), 1.0f);
            float e01 = fminf(__expf(acc[mi][ni][1] - hI0 - hJ1), 1.0f);
            float e10 = fminf(__expf(acc[mi][ni][2] - hI1 - hJ0), 1.0f);
            float e11 = fminf(__expf(acc[mi][ni][3] - hI1 - hJ1), 1.0f);
            if (diagT) {
                if (r0 == c0) e00 = 1.0f;
                if (r0 == c1) e01 = 1.0f;
                if (r1 == c0) e10 = 1.0f;
                if (r1 == c1) e11 = 1.0f;
            }
            if (posT) {
                if (r0 == c0) pos += e00;
                if (r0 == c1) pos += e01;
                if (r1 == c0) pos += e10;
                if (r1 == c1) pos += e11;
            }
            s1 += (e00 + e01) + (e10 + e11);
            s2 = fmaf(e00, e00, s2); s2 = fmaf(e01, e01, s2);
            s2 = fmaf(e10, e10, s2); s2 = fmaf(e11, e11, s2);
            rAcc[mi][0] += e00 + e01;
            rAcc[mi][1] += e10 + e11;
            cAcc[ni][0] += e00 + e10;
            cAcc[ni][1] += e01 + e11;
        }
    }

    // row sums: reduce over qp (lanes sharing a row), lane qp==0 writes
#pragma unroll
    for (int mi = 0; mi < 2; ++mi)
#pragma unroll
        for (int h = 0; h < 2; ++h) {
            float v = rAcc[mi][h];
            v += __shfl_xor_sync(0xffffffffu, v, 1);
            v += __shfl_xor_sync(0xffffffffu, v, 2);
            if (qp == 0)
                atomicAdd(&redRow[warp_m * 32 + mi * 16 + h * 8 + groupID], v);
        }
    // col sums: reduce over groupID, lanes 0..3 write
#pragma unroll
    for (int ni = 0; ni < 8; ++ni)
#pragma unroll
        for (int par = 0; par < 2; ++par) {
            float v = cAcc[ni][par];
            v += __shfl_xor_sync(0xffffffffu, v, 4);
            v += __shfl_xor_sync(0xffffffffu, v, 8);
            v += __shfl_xor_sync(0xffffffffu, v, 16);
            if (lane < 4)
                atomicAdd(&redCol[warp_n * 64 + ni * 8 + 2 * qp + par], v);
        }
    // scalar partials
#pragma unroll
    for (int o = 16; o; o >>= 1) {
        s1  += __shfl_xor_sync(0xffffffffu, s1, o);
        s2  += __shfl_xor_sync(0xffffffffu, s2, o);
        pos += __shfl_xor_sync(0xffffffffu, pos, o);
    }
    if (lane == 0) {
        atomicAdd(&redS[0], s1);
        atomicAdd(&redS[1], s2);
        atomicAdd(&redS[2], pos);
    }
    __syncthreads();

    if (t == 0) {
        double w = diagT ? 1.0 : 2.0;
        atomicAdd(&g_S1, w * (double)redS[0]);
        atomicAdd(&g_S2, w * (double)redS[1]);
        if (posT) atomicAdd(&g_POS, 2.0 * (double)redS[2]);
    }
    if (t < 128) atomicAdd(&g_rowsum[I * BT + t], (double)redRow[t]);
    else if (!diagT) atomicAdd(&g_rowsum[J * BT + t - 128], (double)redCol[t - 128]);
}

// ---------------- final combine ----------------
__global__ void final_kernel(float* out) {
    __shared__ double sh[256];
    int t = threadIdx.x;
    double sr2 = 0.0;
    for (int i = t; i < NROWS; i += 256) { double rv = g_rowsum[i]; sr2 += rv * rv; }
    sh[t] = sr2;
    __syncthreads();
    for (int s = 128; s; s >>= 1) { if (t < s) sh[t] += sh[t + s]; __syncthreads(); }
    if (t == 0) {
        const double Nd = (double)NROWS, Bd = (double)BHALF;
        double S1 = g_S1, S2 = g_S2, POS = g_POS, SR2 = sh[0];
        double trace = Nd;                        // K_ii == 1 exactly
        double neg   = S1 - trace - POS;
        double term1 = POS / (Bd * 2.0);          // B*M*(M-1), M=2
        double term2 = neg / (Bd * Bd * 4.0);     // B^2*M^2
        double scale = Bd / (Bd - 1.0);
        double hsic_zy = scale * (term1 - term2 - 1.0);
        double hsic_zz = (S2 - 2.0 * SR2 / Nd + (S1 / Nd) * (S1 / Nd)) / (Nd * Nd);
        if (hsic_zz < 0.0) hsic_zz = 0.0;
        out[0] = (float)(-hsic_zy + 3.0 * sqrt(hsic_zz));
    }
}

extern "C" void kernel_launch(void* const* d_in, const int* in_sizes, int n_in,
                              void* d_out, int out_size) {
    const float* feat = (const float*)d_in[0];
    float* out = (float*)d_out;

    const int tile_smem = 67712;
    cudaFuncSetAttribute(tile_kernel, cudaFuncAttributeMaxDynamicSharedMemorySize, tile_smem);

    init_kernel<<<(NROWS + 255) / 256, 256>>>();
    norm_kernel<<<(NROWS * 32) / 256, 256>>>(feat);
    convert_kernel<<<(NROWS * 16) / 256, 256>>>(feat);
    dim3 grid(NT, NT);
    tile_kernel<<<grid, 256, tile_smem>>>();
    final_kernel<<<1, 256>>>(out);
}

// round 4
// speedup vs baseline: 7.2628x; 1.0911x over previous
#include <cuda_runtime.h>
#include <cuda_bf16.h>
#include <math.h>
#include <stdint.h>

#define NROWS 8192
#define DIM   128
#define BHALF 4096
#define BT    128
#define NT    (NROWS / BT)          // 64
#define NTILES (NT * (NT + 1) / 2)  // 2080
#define POS_DELTA (BHALF / BT)      // 32

// ---------------- global scratch (no allocations allowed) ----------------
__device__ double g_S1, g_S2, g_POS;
__device__ double g_rowsum[NROWS];
__device__ float  g_h[NROWS];                           // 0.5 * ||x_i||^2 (fp32)
__device__ __align__(16) uint4 g_bf16[NROWS * 16];      // pre-swizzled bf16 rows (256B/row)

// ---------------- fused prep: init scalars/rowsum + norms + bf16 convert ----
__global__ void prep_kernel(const float* __restrict__ feat) {
    int t = blockIdx.x * blockDim.x + threadIdx.x;   // one uint4 (8 bf16) per thread
    int row = t >> 4;
    int chunk = t & 15;
    const float4* src = reinterpret_cast<const float4*>(feat + row * DIM + chunk * 8);
    float4 a = src[0], b = src[1];

    // partial squared norm of these 8 values
    float ss = a.x * a.x + a.y * a.y + a.z * a.z + a.w * a.w
             + b.x * b.x + b.y * b.y + b.z * b.z + b.w * b.w;
#pragma unroll
    for (int o = 1; o < 16; o <<= 1) ss += __shfl_xor_sync(0xffffffffu, ss, o);
    if (chunk == 0) { g_h[row] = 0.5f * ss; g_rowsum[row] = 0.0; }
    if (t == 0) { g_S1 = 0.0; g_S2 = 0.0; g_POS = 0.0; }

    __nv_bfloat162 p0 = __floats2bfloat162_rn(a.x, a.y);
    __nv_bfloat162 p1 = __floats2bfloat162_rn(a.z, a.w);
    __nv_bfloat162 p2 = __floats2bfloat162_rn(b.x, b.y);
    __nv_bfloat162 p3 = __floats2bfloat162_rn(b.z, b.w);
    uint4 v;
    v.x = *reinterpret_cast<uint32_t*>(&p0);
    v.y = *reinterpret_cast<uint32_t*>(&p1);
    v.z = *reinterpret_cast<uint32_t*>(&p2);
    v.w = *reinterpret_cast<uint32_t*>(&p3);
    g_bf16[row * 16 + (chunk ^ (row & 7))] = v;   // 16B-granular XOR swizzle
}

// ---------------- helpers ----------------
__device__ __forceinline__ uint32_t smem_u32(const void* p) {
    uint32_t a;
    asm("{ .reg .u64 t; cvta.to.shared.u64 t, %1; cvt.u32.u64 %0, t; }" : "=r"(a) : "l"(p));
    return a;
}
__device__ __forceinline__ void cp_async16(uint32_t saddr, const void* gaddr) {
    asm volatile("cp.async.cg.shared.global [%0], [%1], 16;" :: "r"(saddr), "l"(gaddr));
}
__device__ __forceinline__ void cp_async_wait_all() {
    asm volatile("cp.async.commit_group;\n\tcp.async.wait_group 0;" ::: "memory");
}
__device__ __forceinline__ void ldmatrix_x4(uint32_t& r0, uint32_t& r1, uint32_t& r2,
                                            uint32_t& r3, uint32_t addr) {
    asm volatile("ldmatrix.sync.aligned.m8n8.x4.shared.b16 {%0,%1,%2,%3}, [%4];"
                 : "=r"(r0), "=r"(r1), "=r"(r2), "=r"(r3) : "r"(addr));
}
__device__ __forceinline__ void mma_bf16(float& c0, float& c1, float& c2, float& c3,
                                         uint32_t a0, uint32_t a1, uint32_t a2, uint32_t a3,
                                         uint32_t b0, uint32_t b1) {
    asm volatile("mma.sync.aligned.m16n8k16.row.col.f32.bf16.bf16.f32 "
                 "{%0,%1,%2,%3}, {%4,%5,%6,%7}, {%8,%9}, {%0,%1,%2,%3};"
                 : "+f"(c0), "+f"(c1), "+f"(c2), "+f"(c3)
                 : "r"(a0), "r"(a1), "r"(a2), "r"(a3), "r"(b0), "r"(b1));
}

// ---------------- fused tile kernel ----------------
// 1D triangular grid: 2080 CTAs, each = one 128x128 tile (J >= I).
// 8 warps in 4(m) x 2(n); each warp 32x64 via 2x8 m16n8k16 fragments.
__global__ __launch_bounds__(256, 2)
void tile_kernel() {
    // decode linear tile id -> (I, J), J >= I
    const int L = blockIdx.x;
    int I = (int)floorf((2.0f * NT + 1.0f
                         - sqrtf((2.0f * NT + 1.0f) * (2.0f * NT + 1.0f) - 8.0f * (float)L))
                        * 0.5f);
    // fixups for fp rounding
    while (I * NT - I * (I - 1) / 2 > L) --I;
    while ((I + 1) * NT - (I + 1) * I / 2 <= L) ++I;
    const int J = I + (L - (I * NT - I * (I - 1) / 2));

    const bool diagT = (I == J);
    const bool posT  = (J == I + POS_DELTA);

    extern __shared__ unsigned char smem[];
    uint4* sA4 = reinterpret_cast<uint4*>(smem);              // 32KB
    uint4* sB4 = reinterpret_cast<uint4*>(smem + 32768);      // 32KB
    float* redRow = reinterpret_cast<float*>(smem + 65536);   // [128]
    float* redCol = reinterpret_cast<float*>(smem + 66048);   // [128]
    float* sHI    = reinterpret_cast<float*>(smem + 66560);   // [128]
    float* sHJ    = reinterpret_cast<float*>(smem + 67072);   // [128]
    float* redS   = reinterpret_cast<float*>(smem + 67584);   // [3]

    const int t = threadIdx.x, wid = t >> 5, lane = t & 31;
    const int warp_m = wid & 3, warp_n = wid >> 2;

    // tile loads: verbatim 16B async copies of the pre-swizzled image
    {
        const uint4* srcA = g_bf16 + I * 2048;
        uint32_t sAbase = smem_u32(sA4);
#pragma unroll
        for (int i = 0; i < 8; ++i)
            cp_async16(sAbase + (i * 256 + t) * 16, srcA + i * 256 + t);
        if (!diagT) {
            const uint4* srcB = g_bf16 + J * 2048;
            uint32_t sBbase = smem_u32(sB4);
#pragma unroll
            for (int i = 0; i < 8; ++i)
                cp_async16(sBbase + (i * 256 + t) * 16, srcB + i * 256 + t);
        }
    }
    if (t < 128) { redRow[t] = 0.f; sHI[t] = g_h[I * BT + t]; }
    else         { redCol[t - 128] = 0.f; sHJ[t - 128] = g_h[J * BT + t - 128]; }
    if (t < 3) redS[t] = 0.f;
    cp_async_wait_all();
    __syncthreads();

    const uint32_t sAa = smem_u32(sA4);
    const uint32_t sBa = diagT ? sAa : smem_u32(sB4);

    const int aRow0 = warp_m * 32 + (lane & 15);
    const int aSub  = lane >> 4;
    const int bRowB = warp_n * 64 + (lane & 7) + ((lane >> 4) << 3);
    const int bSub  = (lane >> 3) & 1;

    float acc[2][8][4];
#pragma unroll
    for (int mi = 0; mi < 2; ++mi)
#pragma unroll
        for (int ni = 0; ni < 8; ++ni)
#pragma unroll
            for (int k = 0; k < 4; ++k) acc[mi][ni][k] = 0.f;

#pragma unroll
    for (int kc = 0; kc < 8; ++kc) {
        uint32_t a[2][4];
#pragma unroll
        for (int mi = 0; mi < 2; ++mi) {
            int row = aRow0 + mi * 16;
            uint32_t addr = sAa + row * 256 + (((2 * kc + aSub) ^ (row & 7)) << 4);
            ldmatrix_x4(a[mi][0], a[mi][1], a[mi][2], a[mi][3], addr);
        }
        uint32_t b[8][2];
#pragma unroll
        for (int p = 0; p < 4; ++p) {
            int row = bRowB + p * 16;
            uint32_t addr = sBa + row * 256 + (((2 * kc + bSub) ^ (row & 7)) << 4);
            uint32_t r0, r1, r2, r3;
            ldmatrix_x4(r0, r1, r2, r3, addr);
            b[2 * p][0] = r0; b[2 * p][1] = r1;
            b[2 * p + 1][0] = r2; b[2 * p + 1][1] = r3;
        }
#pragma unroll
        for (int mi = 0; mi < 2; ++mi)
#pragma unroll
            for (int ni = 0; ni < 8; ++ni)
                mma_bf16(acc[mi][ni][0], acc[mi][ni][1], acc[mi][ni][2], acc[mi][ni][3],
                         a[mi][0], a[mi][1], a[mi][2], a[mi][3], b[ni][0], b[ni][1]);
    }

    // ---- fused epilogue: e = min(exp(dot - hI - hJ), 1); reduce all stats
    const int groupID = lane >> 2, qp = lane & 3;
    float s1 = 0.f, s2 = 0.f, pos = 0.f;
    float rAcc[2][2] = {{0.f, 0.f}, {0.f, 0.f}};
    float cAcc[8][2];
#pragma unroll
    for (int ni = 0; ni < 8; ++ni) { cAcc[ni][0] = 0.f; cAcc[ni][1] = 0.f; }

#pragma unroll
    for (int mi = 0; mi < 2; ++mi) {
        const int r0 = warp_m * 32 + mi * 16 + groupID;
        const int r1 = r0 + 8;
        const float hI0 = sHI[r0], hI1 = sHI[r1];
#pragma unroll
        for (int ni = 0; ni < 8; ++ni) {
            const int c0 = warp_n * 64 + ni * 8 + 2 * qp;
            const int c1 = c0 + 1;
            const float hJ0 = sHJ[c0], hJ1 = sHJ[c1];
            float e00 = fminf(__expf(acc[mi][ni][0] - hI0 - hJ0), 1.0f);
            float e01 = fminf(__expf(acc[mi][ni][1] - hI0 - hJ1), 1.0f);
            float e10 = fminf(__expf(acc[mi][ni][2] - hI1 - hJ0), 1.0f);
            float e11 = fminf(__expf(acc[mi][ni][3] - hI1 - hJ1), 1.0f);
            if (diagT) {
                if (r0 == c0) e00 = 1.0f;
                if (r0 == c1) e01 = 1.0f;
                if (r1 == c0) e10 = 1.0f;
                if (r1 == c1) e11 = 1.0f;
            }
            if (posT) {
                if (r0 == c0) pos += e00;
                if (r0 == c1) pos += e01;
                if (r1 == c0) pos += e10;
                if (r1 == c1) pos += e11;
            }
            s1 += (e00 + e01) + (e10 + e11);
            s2 = fmaf(e00, e00, s2); s2 = fmaf(e01, e01, s2);
            s2 = fmaf(e10, e10, s2); s2 = fmaf(e11, e11, s2);
            rAcc[mi][0] += e00 + e01;
            rAcc[mi][1] += e10 + e11;
            cAcc[ni][0] += e00 + e10;
            cAcc[ni][1] += e01 + e11;
        }
    }

#pragma unroll
    for (int mi = 0; mi < 2; ++mi)
#pragma unroll
        for (int h = 0; h < 2; ++h) {
            float v = rAcc[mi][h];
            v += __shfl_xor_sync(0xffffffffu, v, 1);
            v += __shfl_xor_sync(0xffffffffu, v, 2);
            if (qp == 0)
                atomicAdd(&redRow[warp_m * 32 + mi * 16 + h * 8 + groupID], v);
        }
#pragma unroll
    for (int ni = 0; ni < 8; ++ni)
#pragma unroll
        for (int par = 0; par < 2; ++par) {
            float v = cAcc[ni][par];
            v += __shfl_xor_sync(0xffffffffu, v, 4);
            v += __shfl_xor_sync(0xffffffffu, v, 8);
            v += __shfl_xor_sync(0xffffffffu, v, 16);
            if (lane < 4)
                atomicAdd(&redCol[warp_n * 64 + ni * 8 + 2 * qp + par], v);
        }
#pragma unroll
    for (int o = 16; o; o >>= 1) {
        s1  += __shfl_xor_sync(0xffffffffu, s1, o);
        s2  += __shfl_xor_sync(0xffffffffu, s2, o);
        pos += __shfl_xor_sync(0xffffffffu, pos, o);
    }
    if (lane == 0) {
        atomicAdd(&redS[0], s1);
        atomicAdd(&redS[1], s2);
        atomicAdd(&redS[2], pos);
    }
    __syncthreads();

    if (t == 0) {
        double w = diagT ? 1.0 : 2.0;
        atomicAdd(&g_S1, w * (double)redS[0]);
        atomicAdd(&g_S2, w * (double)redS[1]);
        if (posT) atomicAdd(&g_POS, 2.0 * (double)redS[2]);
    }
    if (t < 128) atomicAdd(&g_rowsum[I * BT + t], (double)redRow[t]);
    else if (!diagT) atomicAdd(&g_rowsum[J * BT + t - 128], (double)redCol[t - 128]);
}

// ---------------- final combine ----------------
__global__ void final_kernel(float* out) {
    __shared__ double sh[1024];
    int t = threadIdx.x;
    double sr2 = 0.0;
#pragma unroll
    for (int i = 0; i < NROWS / 1024; ++i) {
        double rv = g_rowsum[t + 1024 * i];
        sr2 += rv * rv;
    }
    sh[t] = sr2;
    __syncthreads();
    for (int s = 512; s; s >>= 1) { if (t < s) sh[t] += sh[t + s]; __syncthreads(); }
    if (t == 0) {
        const double Nd = (double)NROWS, Bd = (double)BHALF;
        double S1 = g_S1, S2 = g_S2, POS = g_POS, SR2 = sh[0];
        double trace = Nd;                        // K_ii == 1 exactly
        double neg   = S1 - trace - POS;
        double term1 = POS / (Bd * 2.0);          // B*M*(M-1), M=2
        double term2 = neg / (Bd * Bd * 4.0);     // B^2*M^2
        double scale = Bd / (Bd - 1.0);
        double hsic_zy = scale * (term1 - term2 - 1.0);
        double hsic_zz = (S2 - 2.0 * SR2 / Nd + (S1 / Nd) * (S1 / Nd)) / (Nd * Nd);
        if (hsic_zz < 0.0) hsic_zz = 0.0;
        out[0] = (float)(-hsic_zy + 3.0 * sqrt(hsic_zz));
    }
}

extern "C" void kernel_launch(void* const* d_in, const int* in_sizes, int n_in,
                              void* d_out, int out_size) {
    const float* feat = (const float*)d_in[0];
    float* out = (float*)d_out;

    const int tile_smem = 67712;
    cudaFuncSetAttribute(tile_kernel, cudaFuncAttributeMaxDynamicSharedMemorySize, tile_smem);

    prep_kernel<<<(NROWS * 16) / 256, 256>>>(feat);
    tile_kernel<<<NTILES, 256, tile_smem>>>();
    final_kernel<<<1, 1024>>>(out);
}

// round 5
// speedup vs baseline: 7.8956x; 1.0871x over previous
#include <cuda_runtime.h>
#include <cuda_bf16.h>
#include <math.h>
#include <stdint.h>

#define NROWS 8192
#define DIM   128
#define BHALF 4096
#define BT    128
#define NT    (NROWS / BT)          // 64
#define NTILES (NT * (NT + 1) / 2)  // 2080
#define POS_DELTA (BHALF / BT)      // 32
#define LOG2E 1.4426950408889634f

// ---------------- global scratch (no allocations allowed) ----------------
__device__ double g_S2, g_POS;
__device__ double g_rowsum[NROWS];
__device__ float  g_nh[NROWS];                          // -0.5*||x_i||^2 * log2e
__device__ __align__(16) uint4 g_bf16[NROWS * 16];      // pre-swizzled bf16 rows (256B/row)

// ---------------- fused prep: init + norms + bf16 convert ----------------
__global__ void prep_kernel(const float* __restrict__ feat) {
    int t = blockIdx.x * blockDim.x + threadIdx.x;   // one uint4 (8 bf16) per thread
    int row = t >> 4;
    int chunk = t & 15;
    const float4* src = reinterpret_cast<const float4*>(feat + row * DIM + chunk * 8);
    float4 a = src[0], b = src[1];

    float ss = a.x * a.x + a.y * a.y + a.z * a.z + a.w * a.w
             + b.x * b.x + b.y * b.y + b.z * b.z + b.w * b.w;
#pragma unroll
    for (int o = 1; o < 16; o <<= 1) ss += __shfl_xor_sync(0xffffffffu, ss, o);
    if (chunk == 0) { g_nh[row] = -0.5f * LOG2E * ss; g_rowsum[row] = 0.0; }
    if (t == 0) { g_S2 = 0.0; g_POS = 0.0; }

    __nv_bfloat162 p0 = __floats2bfloat162_rn(a.x, a.y);
    __nv_bfloat162 p1 = __floats2bfloat162_rn(a.z, a.w);
    __nv_bfloat162 p2 = __floats2bfloat162_rn(b.x, b.y);
    __nv_bfloat162 p3 = __floats2bfloat162_rn(b.z, b.w);
    uint4 v;
    v.x = *reinterpret_cast<uint32_t*>(&p0);
    v.y = *reinterpret_cast<uint32_t*>(&p1);
    v.z = *reinterpret_cast<uint32_t*>(&p2);
    v.w = *reinterpret_cast<uint32_t*>(&p3);
    g_bf16[row * 16 + (chunk ^ (row & 7))] = v;   // 16B-granular XOR swizzle
}

// ---------------- helpers ----------------
__device__ __forceinline__ uint32_t smem_u32(const void* p) {
    uint32_t a;
    asm("{ .reg .u64 t; cvta.to.shared.u64 t, %1; cvt.u32.u64 %0, t; }" : "=r"(a) : "l"(p));
    return a;
}
__device__ __forceinline__ void cp_async16(uint32_t saddr, const void* gaddr) {
    asm volatile("cp.async.cg.shared.global [%0], [%1], 16;" :: "r"(saddr), "l"(gaddr));
}
__device__ __forceinline__ void cp_async_wait_all() {
    asm volatile("cp.async.commit_group;\n\tcp.async.wait_group 0;" ::: "memory");
}
__device__ __forceinline__ void ldmatrix_x4(uint32_t& r0, uint32_t& r1, uint32_t& r2,
                                            uint32_t& r3, uint32_t addr) {
    asm volatile("ldmatrix.sync.aligned.m8n8.x4.shared.b16 {%0,%1,%2,%3}, [%4];"
                 : "=r"(r0), "=r"(r1), "=r"(r2), "=r"(r3) : "r"(addr));
}
__device__ __forceinline__ void mma_bf16(float& c0, float& c1, float& c2, float& c3,
                                         uint32_t a0, uint32_t a1, uint32_t a2, uint32_t a3,
                                         uint32_t b0, uint32_t b1) {
    asm volatile("mma.sync.aligned.m16n8k16.row.col.f32.bf16.bf16.f32 "
                 "{%0,%1,%2,%3}, {%4,%5,%6,%7}, {%8,%9}, {%0,%1,%2,%3};"
                 : "+f"(c0), "+f"(c1), "+f"(c2), "+f"(c3)
                 : "r"(a0), "r"(a1), "r"(a2), "r"(a3), "r"(b0), "r"(b1));
}
__device__ __forceinline__ float ex2f(float x) {
    float r; asm("ex2.approx.f32 %0, %1;" : "=f"(r) : "f"(x)); return r;
}
// packed f32x2 (base PTX, sm_100+): carriers are u64
__device__ __forceinline__ unsigned long long packf2(float lo, float hi) {
    unsigned long long r;
    asm("mov.b64 %0, {%1, %2};" : "=l"(r) : "f"(lo), "f"(hi));
    return r;
}
__device__ __forceinline__ void unpackf2(unsigned long long v, float& lo, float& hi) {
    asm("mov.b64 {%0, %1}, %2;" : "=f"(lo), "=f"(hi) : "l"(v));
}
__device__ __forceinline__ void fma2acc(unsigned long long& acc, unsigned long long a,
                                        unsigned long long b) {
    asm("fma.rn.f32x2 %0, %1, %2, %0;" : "+l"(acc) : "l"(a), "l"(b));
}
__device__ __forceinline__ void add2acc(unsigned long long& acc, unsigned long long a) {
    asm("add.rn.f32x2 %0, %1, %2;" : "=l"(acc) : "l"(a), "l"(acc));
}

// ---------------- fused half-tile kernel ----------------
// grid = (2080, 2): blockIdx.x = triangular tile (I,J), blockIdx.y = column half.
// CTA = 128 threads (4 warps), computes 128 rows x 64 cols.
__global__ __launch_bounds__(128, 4)
void tile_kernel() {
    const int L = blockIdx.x;
    int I = (int)floorf((2.0f * NT + 1.0f
                         - sqrtf((2.0f * NT + 1.0f) * (2.0f * NT + 1.0f) - 8.0f * (float)L))
                        * 0.5f);
    while (I * NT - I * (I - 1) / 2 > L) --I;
    while ((I + 1) * NT - (I + 1) * I / 2 <= L) ++I;
    const int J = I + (L - (I * NT - I * (I - 1) / 2));
    const int half = blockIdx.y;

    const bool diagT = (I == J);
    const bool posT  = (J == I + POS_DELTA);

    extern __shared__ unsigned char smem[];
    uint4* sA4 = reinterpret_cast<uint4*>(smem);              // 32KB (128 rows)
    uint4* sB4 = reinterpret_cast<uint4*>(smem + 32768);      // 16KB (64 rows)
    float* redRow = reinterpret_cast<float*>(smem + 49152);   // [128]
    float* redCol = reinterpret_cast<float*>(smem + 49664);   // [64]
    float* sNHI   = reinterpret_cast<float*>(smem + 49920);   // [128]
    float* sNHJ   = reinterpret_cast<float*>(smem + 50432);   // [64]
    float* redS   = reinterpret_cast<float*>(smem + 50688);   // [2]: s2, pos

    const int t = threadIdx.x, wid = t >> 5, lane = t & 31;

    // fills: A = rows of block I (verbatim pre-swizzled), B = 64-row half of block J
    {
        const uint4* srcA = g_bf16 + I * 2048;
        uint32_t sAbase = smem_u32(sA4);
#pragma unroll
        for (int i = 0; i < 16; ++i)
            cp_async16(sAbase + (i * 128 + t) * 16, srcA + i * 128 + t);
        const uint4* srcB = g_bf16 + J * 2048 + half * 1024;
        uint32_t sBbase = smem_u32(sB4);
#pragma unroll
        for (int i = 0; i < 8; ++i)
            cp_async16(sBbase + (i * 128 + t) * 16, srcB + i * 128 + t);
    }
    redRow[t] = 0.f;
    sNHI[t] = g_nh[I * BT + t];
    if (t < 64) { redCol[t] = 0.f; sNHJ[t] = g_nh[J * BT + half * 64 + t]; }
    if (t < 2) redS[t] = 0.f;
    cp_async_wait_all();
    __syncthreads();

    const uint32_t sAa = smem_u32(sA4);
    const uint32_t sBa = smem_u32(sB4);

    const int aRow0 = wid * 32 + (lane & 15);
    const int aSub  = lane >> 4;
    const int bRowB = (lane & 7) + ((lane >> 4) << 3);
    const int bSub  = (lane >> 3) & 1;

    float acc[2][8][4];
#pragma unroll
    for (int mi = 0; mi < 2; ++mi)
#pragma unroll
        for (int ni = 0; ni < 8; ++ni)
#pragma unroll
            for (int k = 0; k < 4; ++k) acc[mi][ni][k] = 0.f;

#pragma unroll
    for (int kc = 0; kc < 8; ++kc) {
        uint32_t a[2][4];
#pragma unroll
        for (int mi = 0; mi < 2; ++mi) {
            int row = aRow0 + mi * 16;
            uint32_t addr = sAa + row * 256 + (((2 * kc + aSub) ^ (row & 7)) << 4);
            ldmatrix_x4(a[mi][0], a[mi][1], a[mi][2], a[mi][3], addr);
        }
        uint32_t b[8][2];
#pragma unroll
        for (int p = 0; p < 4; ++p) {
            int row = bRowB + p * 16;   // local B row; global row = J*128+half*64+row (same &7)
            uint32_t addr = sBa + row * 256 + (((2 * kc + bSub) ^ (row & 7)) << 4);
            uint32_t r0, r1, r2, r3;
            ldmatrix_x4(r0, r1, r2, r3, addr);
            b[2 * p][0] = r0; b[2 * p][1] = r1;
            b[2 * p + 1][0] = r2; b[2 * p + 1][1] = r3;
        }
#pragma unroll
        for (int mi = 0; mi < 2; ++mi)
#pragma unroll
            for (int ni = 0; ni < 8; ++ni)
                mma_bf16(acc[mi][ni][0], acc[mi][ni][1], acc[mi][ni][2], acc[mi][ni][3],
                         a[mi][0], a[mi][1], a[mi][2], a[mi][3], b[ni][0], b[ni][1]);
    }

    // ---- fused epilogue: e = min(ex2(dot*log2e + nhI + nhJ), 1)
    const int groupID = lane >> 2, qp = lane & 3;
    float pos = 0.f;
    unsigned long long s2p = 0ull;
    unsigned long long rAcc[2][2] = {{0ull, 0ull}, {0ull, 0ull}};
    unsigned long long cAcc[8];
#pragma unroll
    for (int ni = 0; ni < 8; ++ni) cAcc[ni] = 0ull;

    // preload per-thread column norms (16 scalars)
    float nhJ0[8], nhJ1[8];
#pragma unroll
    for (int ni = 0; ni < 8; ++ni) {
        nhJ0[ni] = sNHJ[ni * 8 + 2 * qp];
        nhJ1[ni] = sNHJ[ni * 8 + 2 * qp + 1];
    }

#pragma unroll
    for (int mi = 0; mi < 2; ++mi) {
        const int r0 = wid * 32 + mi * 16 + groupID;
        const int r1 = r0 + 8;
        const float nhI0 = sNHI[r0], nhI1 = sNHI[r1];
#pragma unroll
        for (int ni = 0; ni < 8; ++ni) {
            const int c0 = ni * 8 + 2 * qp;             // local col; global col = half*64+c0
            const int c1 = c0 + 1;
            float e00 = fminf(ex2f(fmaf(acc[mi][ni][0], LOG2E, nhI0) + nhJ0[ni]), 1.0f);
            float e01 = fminf(ex2f(fmaf(acc[mi][ni][1], LOG2E, nhI0) + nhJ1[ni]), 1.0f);
            float e10 = fminf(ex2f(fmaf(acc[mi][ni][2], LOG2E, nhI1) + nhJ0[ni]), 1.0f);
            float e11 = fminf(ex2f(fmaf(acc[mi][ni][3], LOG2E, nhI1) + nhJ1[ni]), 1.0f);
            const int g0 = half * 64 + c0, g1 = half * 64 + c1;  // tile-local global cols
            if (diagT) {
                if (r0 == g0) e00 = 1.0f;
                if (r0 == g1) e01 = 1.0f;
                if (r1 == g0) e10 = 1.0f;
                if (r1 == g1) e11 = 1.0f;
            }
            if (posT) {
                if (r0 == g0) pos += e00;
                if (r0 == g1) pos += e01;
                if (r1 == g0) pos += e10;
                if (r1 == g1) pos += e11;
            }
            unsigned long long p0 = packf2(e00, e01);   // row r0 pair (cols c0,c1)
            unsigned long long p1 = packf2(e10, e11);   // row r1 pair
            fma2acc(s2p, p0, p0);
            fma2acc(s2p, p1, p1);
            add2acc(rAcc[mi][0], p0);
            add2acc(rAcc[mi][1], p1);
            add2acc(cAcc[ni], p0);
            add2acc(cAcc[ni], p1);
        }
    }

    // row sums: each row owned by exactly one (wid, mi, h, groupID) -> plain store
#pragma unroll
    for (int mi = 0; mi < 2; ++mi)
#pragma unroll
        for (int h = 0; h < 2; ++h) {
            float lo, hi; unpackf2(rAcc[mi][h], lo, hi);
            float v = lo + hi;
            v += __shfl_xor_sync(0xffffffffu, v, 1);
            v += __shfl_xor_sync(0xffffffffu, v, 2);
            if (qp == 0) redRow[wid * 32 + mi * 16 + h * 8 + groupID] = v;
        }
    // col sums: reduce over groupID; 4 warps share cols -> smem atomics
#pragma unroll
    for (int ni = 0; ni < 8; ++ni) {
        float lo, hi; unpackf2(cAcc[ni], lo, hi);
#pragma unroll
        for (int o = 4; o < 32; o <<= 1) {
            lo += __shfl_xor_sync(0xffffffffu, lo, o);
            hi += __shfl_xor_sync(0xffffffffu, hi, o);
        }
        if (lane < 4) {
            atomicAdd(&redCol[ni * 8 + 2 * qp], lo);
            atomicAdd(&redCol[ni * 8 + 2 * qp + 1], hi);
        }
    }
    // scalars
    {
        float lo, hi; unpackf2(s2p, lo, hi);
        float s2 = lo + hi;
#pragma unroll
        for (int o = 16; o; o >>= 1) {
            s2  += __shfl_xor_sync(0xffffffffu, s2, o);
            pos += __shfl_xor_sync(0xffffffffu, pos, o);
        }
        if (lane == 0) {
            atomicAdd(&redS[0], s2);
            if (posT) atomicAdd(&redS[1], pos);
        }
    }
    __syncthreads();

    if (t == 0) {
        double w = diagT ? 1.0 : 2.0;
        atomicAdd(&g_S2, w * (double)redS[0]);
        if (posT) atomicAdd(&g_POS, 2.0 * (double)redS[1]);
    }
    atomicAdd(&g_rowsum[I * BT + t], (double)redRow[t]);
    if (t < 64 && !diagT)
        atomicAdd(&g_rowsum[J * BT + half * 64 + t], (double)redCol[t]);
}

// ---------------- final combine ----------------
__global__ void final_kernel(float* out) {
    __shared__ double sh1[1024];
    __shared__ double sh2[1024];
    int t = threadIdx.x;
    double sr1 = 0.0, sr2 = 0.0;
#pragma unroll
    for (int i = 0; i < NROWS / 1024; ++i) {
        double rv = g_rowsum[t + 1024 * i];
        sr1 += rv;
        sr2 += rv * rv;
    }
    sh1[t] = sr1; sh2[t] = sr2;
    __syncthreads();
    for (int s = 512; s; s >>= 1) {
        if (t < s) { sh1[t] += sh1[t + s]; sh2[t] += sh2[t + s]; }
        __syncthreads();
    }
    if (t == 0) {
        const double Nd = (double)NROWS, Bd = (double)BHALF;
        double S1 = sh1[0];                       // sum over full K
        double S2 = g_S2, POS = g_POS, SR2 = sh2[0];
        double trace = Nd;                        // K_ii == 1 exactly
        double neg   = S1 - trace - POS;
        double term1 = POS / (Bd * 2.0);          // B*M*(M-1), M=2
        double term2 = neg / (Bd * Bd * 4.0);     // B^2*M^2
        double scale = Bd / (Bd - 1.0);
        double hsic_zy = scale * (term1 - term2 - 1.0);
        double hsic_zz = (S2 - 2.0 * SR2 / Nd + (S1 / Nd) * (S1 / Nd)) / (Nd * Nd);
        if (hsic_zz < 0.0) hsic_zz = 0.0;
        out[0] = (float)(-hsic_zy + 3.0 * sqrt(hsic_zz));
    }
}

extern "C" void kernel_launch(void* const* d_in, const int* in_sizes, int n_in,
                              void* d_out, int out_size) {
    const float* feat = (const float*)d_in[0];
    float* out = (float*)d_out;

    const int tile_smem = 50696;
    cudaFuncSetAttribute(tile_kernel, cudaFuncAttributeMaxDynamicSharedMemorySize, tile_smem);

    prep_kernel<<<(NROWS * 16) / 512, 512>>>(feat);
    dim3 grid(NTILES, 2);
    tile_kernel<<<grid, 128, tile_smem>>>();
    final_kernel<<<1, 1024>>>(out);
}

// round 6
// speedup vs baseline: 8.3330x; 1.0554x over previous
#include <cuda_runtime.h>
#include <cuda_bf16.h>
#include <math.h>
#include <stdint.h>

#define NROWS 8192
#define DIM   128
#define BHALF 4096
#define BT    128
#define NT    (NROWS / BT)          // 64
#define NTILES (NT * (NT + 1) / 2)  // 2080
#define POS_DELTA (BHALF / BT)      // 32
#define LOG2E 1.4426950408889634f

// ---------------- global scratch (no allocations allowed) ----------------
__device__ double g_S2, g_POS;
__device__ double g_rowsum[NROWS];
__device__ __align__(16) uint4 g_bf16[NROWS * 16];      // pre-swizzled bf16 rows (256B/row)

// ---------------- prep: init + bf16 convert (norms are exactly 0.5: l2-normalized)
__global__ void prep_kernel(const float* __restrict__ feat) {
    int t = blockIdx.x * blockDim.x + threadIdx.x;   // one uint4 (8 bf16) per thread
    int row = t >> 4;
    int chunk = t & 15;
    const float4* src = reinterpret_cast<const float4*>(feat + row * DIM + chunk * 8);
    float4 a = src[0], b = src[1];
    if (chunk == 0) g_rowsum[row] = 0.0;
    if (t == 0) { g_S2 = 0.0; g_POS = 0.0; }

    __nv_bfloat162 p0 = __floats2bfloat162_rn(a.x, a.y);
    __nv_bfloat162 p1 = __floats2bfloat162_rn(a.z, a.w);
    __nv_bfloat162 p2 = __floats2bfloat162_rn(b.x, b.y);
    __nv_bfloat162 p3 = __floats2bfloat162_rn(b.z, b.w);
    uint4 v;
    v.x = *reinterpret_cast<uint32_t*>(&p0);
    v.y = *reinterpret_cast<uint32_t*>(&p1);
    v.z = *reinterpret_cast<uint32_t*>(&p2);
    v.w = *reinterpret_cast<uint32_t*>(&p3);
    g_bf16[row * 16 + (chunk ^ (row & 7))] = v;   // 16B-granular XOR swizzle
}

// ---------------- helpers ----------------
__device__ __forceinline__ uint32_t smem_u32(const void* p) {
    uint32_t a;
    asm("{ .reg .u64 t; cvta.to.shared.u64 t, %1; cvt.u32.u64 %0, t; }" : "=r"(a) : "l"(p));
    return a;
}
__device__ __forceinline__ void cp_async16(uint32_t saddr, const void* gaddr) {
    asm volatile("cp.async.cg.shared.global [%0], [%1], 16;" :: "r"(saddr), "l"(gaddr));
}
__device__ __forceinline__ void cp_async_wait_all() {
    asm volatile("cp.async.commit_group;\n\tcp.async.wait_group 0;" ::: "memory");
}
__device__ __forceinline__ void ldmatrix_x4(uint32_t& r0, uint32_t& r1, uint32_t& r2,
                                            uint32_t& r3, uint32_t addr) {
    asm volatile("ldmatrix.sync.aligned.m8n8.x4.shared.b16 {%0,%1,%2,%3}, [%4];"
                 : "=r"(r0), "=r"(r1), "=r"(r2), "=r"(r3) : "r"(addr));
}
__device__ __forceinline__ void mma_bf16(float& c0, float& c1, float& c2, float& c3,
                                         uint32_t a0, uint32_t a1, uint32_t a2, uint32_t a3,
                                         uint32_t b0, uint32_t b1) {
    asm volatile("mma.sync.aligned.m16n8k16.row.col.f32.bf16.bf16.f32 "
                 "{%0,%1,%2,%3}, {%4,%5,%6,%7}, {%8,%9}, {%0,%1,%2,%3};"
                 : "+f"(c0), "+f"(c1), "+f"(c2), "+f"(c3)
                 : "r"(a0), "r"(a1), "r"(a2), "r"(a3), "r"(b0), "r"(b1));
}
__device__ __forceinline__ float ex2f(float x) {
    float r; asm("ex2.approx.f32 %0, %1;" : "=f"(r) : "f"(x)); return r;
}
__device__ __forceinline__ unsigned long long packf2(float lo, float hi) {
    unsigned long long r;
    asm("mov.b64 %0, {%1, %2};" : "=l"(r) : "f"(lo), "f"(hi));
    return r;
}
__device__ __forceinline__ void unpackf2(unsigned long long v, float& lo, float& hi) {
    asm("mov.b64 {%0, %1}, %2;" : "=f"(lo), "=f"(hi) : "l"(v));
}
__device__ __forceinline__ void fma2acc(unsigned long long& acc, unsigned long long a,
                                        unsigned long long b) {
    asm("fma.rn.f32x2 %0, %1, %2, %0;" : "+l"(acc) : "l"(a), "l"(b));
}
__device__ __forceinline__ void add2acc(unsigned long long& acc, unsigned long long a) {
    asm("add.rn.f32x2 %0, %1, %2;" : "=l"(acc) : "l"(a), "l"(acc));
}

// ---------------- epilogue (templated: SPECIAL = diag or pos tile) ----------
template<bool SPECIAL>
__device__ __forceinline__ void epilogue(float (&acc)[2][8][4],
                                         int wid, int lane, int half,
                                         bool diagT, bool posT,
                                         float* redRow, float* redCol, float* redS) {
    const int groupID = lane >> 2, qp = lane & 3;
    float pos = 0.f;
    unsigned long long s2p = 0ull;
    unsigned long long rAcc[2][2] = {{0ull, 0ull}, {0ull, 0ull}};
    unsigned long long cAcc[8];
#pragma unroll
    for (int ni = 0; ni < 8; ++ni) cAcc[ni] = 0ull;

#pragma unroll
    for (int mi = 0; mi < 2; ++mi) {
        const int r0 = wid * 32 + mi * 16 + groupID;
        const int r1 = r0 + 8;
#pragma unroll
        for (int ni = 0; ni < 8; ++ni) {
            float e00 = ex2f(fmaf(acc[mi][ni][0], LOG2E, -LOG2E));
            float e01 = ex2f(fmaf(acc[mi][ni][1], LOG2E, -LOG2E));
            float e10 = ex2f(fmaf(acc[mi][ni][2], LOG2E, -LOG2E));
            float e11 = ex2f(fmaf(acc[mi][ni][3], LOG2E, -LOG2E));
            if (SPECIAL) {
                e00 = fminf(e00, 1.0f); e01 = fminf(e01, 1.0f);
                e10 = fminf(e10, 1.0f); e11 = fminf(e11, 1.0f);
                const int g0 = half * 64 + ni * 8 + 2 * qp, g1 = g0 + 1;
                if (diagT) {
                    if (r0 == g0) e00 = 1.0f;
                    if (r0 == g1) e01 = 1.0f;
                    if (r1 == g0) e10 = 1.0f;
                    if (r1 == g1) e11 = 1.0f;
                }
                if (posT) {
                    if (r0 == g0) pos += e00;
                    if (r0 == g1) pos += e01;
                    if (r1 == g0) pos += e10;
                    if (r1 == g1) pos += e11;
                }
            }
            unsigned long long p0 = packf2(e00, e01);
            unsigned long long p1 = packf2(e10, e11);
            fma2acc(s2p, p0, p0);
            fma2acc(s2p, p1, p1);
            add2acc(rAcc[mi][0], p0);
            add2acc(rAcc[mi][1], p1);
            add2acc(cAcc[ni], p0);
            add2acc(cAcc[ni], p1);
        }
    }

    // row sums: each row owned by one (wid, mi, h, groupID) -> plain store
#pragma unroll
    for (int mi = 0; mi < 2; ++mi)
#pragma unroll
        for (int h = 0; h < 2; ++h) {
            float lo, hi; unpackf2(rAcc[mi][h], lo, hi);
            float v = lo + hi;
            v += __shfl_xor_sync(0xffffffffu, v, 1);
            v += __shfl_xor_sync(0xffffffffu, v, 2);
            if (qp == 0) redRow[wid * 32 + mi * 16 + h * 8 + groupID] = v;
        }
    // col sums: reduce over groupID; 4 warps share cols -> smem atomics
#pragma unroll
    for (int ni = 0; ni < 8; ++ni) {
        float lo, hi; unpackf2(cAcc[ni], lo, hi);
#pragma unroll
        for (int o = 4; o < 32; o <<= 1) {
            lo += __shfl_xor_sync(0xffffffffu, lo, o);
            hi += __shfl_xor_sync(0xffffffffu, hi, o);
        }
        if (lane < 4) {
            atomicAdd(&redCol[ni * 8 + 2 * qp], lo);
            atomicAdd(&redCol[ni * 8 + 2 * qp + 1], hi);
        }
    }
    // scalars
    {
        float lo, hi; unpackf2(s2p, lo, hi);
        float s2 = lo + hi;
#pragma unroll
        for (int o = 16; o; o >>= 1) {
            s2 += __shfl_xor_sync(0xffffffffu, s2, o);
            if (SPECIAL) pos += __shfl_xor_sync(0xffffffffu, pos, o);
        }
        if (lane == 0) {
            atomicAdd(&redS[0], s2);
            if (SPECIAL && posT) atomicAdd(&redS[1], pos);
        }
    }
}

// ---------------- fused half-tile kernel ----------------
// grid = (2080, 2): blockIdx.x = triangular tile (I,J), blockIdx.y = column half.
// CTA = 128 threads (4 warps), computes 128 rows x 64 cols.
__global__ __launch_bounds__(128, 4)
void tile_kernel() {
    const int L = blockIdx.x;
    int I = (int)floorf((2.0f * NT + 1.0f
                         - sqrtf((2.0f * NT + 1.0f) * (2.0f * NT + 1.0f) - 8.0f * (float)L))
                        * 0.5f);
    while (I * NT - I * (I - 1) / 2 > L) --I;
    while ((I + 1) * NT - (I + 1) * I / 2 <= L) ++I;
    const int J = I + (L - (I * NT - I * (I - 1) / 2));
    const int half = blockIdx.y;

    const bool diagT = (I == J);
    const bool posT  = (J == I + POS_DELTA);

    extern __shared__ unsigned char smem[];
    uint4* sA4 = reinterpret_cast<uint4*>(smem);              // 32KB (128 rows)
    uint4* sB4 = reinterpret_cast<uint4*>(smem + 32768);      // 16KB (64 rows)
    float* redRow = reinterpret_cast<float*>(smem + 49152);   // [128]
    float* redCol = reinterpret_cast<float*>(smem + 49664);   // [64]
    float* redS   = reinterpret_cast<float*>(smem + 49920);   // [2]: s2, pos

    const int t = threadIdx.x, wid = t >> 5, lane = t & 31;

    {
        const uint4* srcA = g_bf16 + I * 2048;
        uint32_t sAbase = smem_u32(sA4);
#pragma unroll
        for (int i = 0; i < 16; ++i)
            cp_async16(sAbase + (i * 128 + t) * 16, srcA + i * 128 + t);
        const uint4* srcB = g_bf16 + J * 2048 + half * 1024;
        uint32_t sBbase = smem_u32(sB4);
#pragma unroll
        for (int i = 0; i < 8; ++i)
            cp_async16(sBbase + (i * 128 + t) * 16, srcB + i * 128 + t);
    }
    redRow[t] = 0.f;
    if (t < 64) redCol[t] = 0.f;
    if (t < 2) redS[t] = 0.f;
    cp_async_wait_all();
    __syncthreads();

    const uint32_t sAa = smem_u32(sA4);
    const uint32_t sBa = smem_u32(sB4);

    const int aRow0 = wid * 32 + (lane & 15);
    const int aSub  = lane >> 4;
    const int bRowB = (lane & 7) + ((lane >> 4) << 3);
    const int bSub  = (lane >> 3) & 1;

    float acc[2][8][4];
#pragma unroll
    for (int mi = 0; mi < 2; ++mi)
#pragma unroll
        for (int ni = 0; ni < 8; ++ni)
#pragma unroll
            for (int k = 0; k < 4; ++k) acc[mi][ni][k] = 0.f;

#pragma unroll
    for (int kc = 0; kc < 8; ++kc) {
        uint32_t a[2][4];
#pragma unroll
        for (int mi = 0; mi < 2; ++mi) {
            int row = aRow0 + mi * 16;
            uint32_t addr = sAa + row * 256 + (((2 * kc + aSub) ^ (row & 7)) << 4);
            ldmatrix_x4(a[mi][0], a[mi][1], a[mi][2], a[mi][3], addr);
        }
        uint32_t b[8][2];
#pragma unroll
        for (int p = 0; p < 4; ++p) {
            int row = bRowB + p * 16;
            uint32_t addr = sBa + row * 256 + (((2 * kc + bSub) ^ (row & 7)) << 4);
            uint32_t r0, r1, r2, r3;
            ldmatrix_x4(r0, r1, r2, r3, addr);
            b[2 * p][0] = r0; b[2 * p][1] = r1;
            b[2 * p + 1][0] = r2; b[2 * p + 1][1] = r3;
        }
#pragma unroll
        for (int mi = 0; mi < 2; ++mi)
#pragma unroll
            for (int ni = 0; ni < 8; ++ni)
                mma_bf16(acc[mi][ni][0], acc[mi][ni][1], acc[mi][ni][2], acc[mi][ni][3],
                         a[mi][0], a[mi][1], a[mi][2], a[mi][3], b[ni][0], b[ni][1]);
    }

    if (diagT || posT)
        epilogue<true>(acc, wid, lane, half, diagT, posT, redRow, redCol, redS);
    else
        epilogue<false>(acc, wid, lane, half, diagT, posT, redRow, redCol, redS);
    __syncthreads();

    if (t == 0) {
        double w = diagT ? 1.0 : 2.0;
        atomicAdd(&g_S2, w * (double)redS[0]);
        if (posT) atomicAdd(&g_POS, 2.0 * (double)redS[1]);
    }
    atomicAdd(&g_rowsum[I * BT + t], (double)redRow[t]);
    if (t < 64 && !diagT)
        atomicAdd(&g_rowsum[J * BT + half * 64 + t], (double)redCol[t]);
}

// ---------------- final combine ----------------
__global__ void final_kernel(float* out) {
    __shared__ double sh1[1024];
    __shared__ double sh2[1024];
    int t = threadIdx.x;
    double sr1 = 0.0, sr2 = 0.0;
#pragma unroll
    for (int i = 0; i < NROWS / 1024; ++i) {
        double rv = g_rowsum[t + 1024 * i];
        sr1 += rv;
        sr2 += rv * rv;
    }
    sh1[t] = sr1; sh2[t] = sr2;
    __syncthreads();
    for (int s = 512; s; s >>= 1) {
        if (t < s) { sh1[t] += sh1[t + s]; sh2[t] += sh2[t + s]; }
        __syncthreads();
    }
    if (t == 0) {
        const double Nd = (double)NROWS, Bd = (double)BHALF;
        double S1 = sh1[0];
        double S2 = g_S2, POS = g_POS, SR2 = sh2[0];
        double trace = Nd;                        // K_ii == 1 exactly
        double neg   = S1 - trace - POS;
        double term1 = POS / (Bd * 2.0);          // B*M*(M-1), M=2
        double term2 = neg / (Bd * Bd * 4.0);     // B^2*M^2
        double scale = Bd / (Bd - 1.0);
        double hsic_zy = scale * (term1 - term2 - 1.0);
        double hsic_zz = (S2 - 2.0 * SR2 / Nd + (S1 / Nd) * (S1 / Nd)) / (Nd * Nd);
        if (hsic_zz < 0.0) hsic_zz = 0.0;
        out[0] = (float)(-hsic_zy + 3.0 * sqrt(hsic_zz));
    }
}

extern "C" void kernel_launch(void* const* d_in, const int* in_sizes, int n_in,
                              void* d_out, int out_size) {
    const float* feat = (const float*)d_in[0];
    float* out = (float*)d_out;

    const int tile_smem = 49936;
    cudaFuncSetAttribute(tile_kernel, cudaFuncAttributeMaxDynamicSharedMemorySize, tile_smem);

    prep_kernel<<<(NROWS * 16) / 512, 512>>>(feat);
    dim3 grid(NTILES, 2);
    tile_kernel<<<grid, 128, tile_smem>>>();
    final_kernel<<<1, 1024>>>(out);
}

// round 7
// speedup vs baseline: 9.3592x; 1.1232x over previous
#include <cuda_runtime.h>
#include <cuda_bf16.h>
#include <math.h>
#include <stdint.h>

#define NROWS 8192
#define DIM   128
#define BHALF 4096
#define BT    128
#define NT    (NROWS / BT)          // 64
#define NTILES (NT * (NT + 1) / 2)  // 2080
#define POS_DELTA (BHALF / BT)      // 32
#define LOG2E 1.4426950408889634f

// ---------------- global scratch (no allocations allowed) ----------------
__device__ double g_S2, g_POS, g_R1, g_R2;
__device__ double g_rowsum[NROWS];
__device__ __align__(16) uint4 g_bf16[NROWS * 16];      // pre-swizzled bf16 rows (256B/row)

// ---------------- prep: init + bf16 convert (norms == 0.5 exactly: l2-normalized)
__global__ void prep_kernel(const float* __restrict__ feat) {
    int t = blockIdx.x * blockDim.x + threadIdx.x;   // one uint4 (8 bf16) per thread
    int row = t >> 4;
    int chunk = t & 15;
    const float4* src = reinterpret_cast<const float4*>(feat + row * DIM + chunk * 8);
    float4 a = src[0], b = src[1];
    if (chunk == 0) g_rowsum[row] = 0.0;
    if (t == 0) { g_S2 = 0.0; g_POS = 0.0; g_R1 = 0.0; g_R2 = 0.0; }

    __nv_bfloat162 p0 = __floats2bfloat162_rn(a.x, a.y);
    __nv_bfloat162 p1 = __floats2bfloat162_rn(a.z, a.w);
    __nv_bfloat162 p2 = __floats2bfloat162_rn(b.x, b.y);
    __nv_bfloat162 p3 = __floats2bfloat162_rn(b.z, b.w);
    uint4 v;
    v.x = *reinterpret_cast<uint32_t*>(&p0);
    v.y = *reinterpret_cast<uint32_t*>(&p1);
    v.z = *reinterpret_cast<uint32_t*>(&p2);
    v.w = *reinterpret_cast<uint32_t*>(&p3);
    g_bf16[row * 16 + (chunk ^ (row & 7))] = v;   // 16B-granular XOR swizzle
}

// ---------------- helpers ----------------
__device__ __forceinline__ uint32_t smem_u32(const void* p) {
    uint32_t a;
    asm("{ .reg .u64 t; cvta.to.shared.u64 t, %1; cvt.u32.u64 %0, t; }" : "=r"(a) : "l"(p));
    return a;
}
__device__ __forceinline__ void cp_async16(uint32_t saddr, const void* gaddr) {
    asm volatile("cp.async.cg.shared.global [%0], [%1], 16;" :: "r"(saddr), "l"(gaddr));
}
__device__ __forceinline__ void cp_commit() {
    asm volatile("cp.async.commit_group;" ::: "memory");
}
__device__ __forceinline__ void cp_wait_all() {
    asm volatile("cp.async.wait_group 0;" ::: "memory");
}
__device__ __forceinline__ void ldmatrix_x4(uint32_t& r0, uint32_t& r1, uint32_t& r2,
                                            uint32_t& r3, uint32_t addr) {
    asm volatile("ldmatrix.sync.aligned.m8n8.x4.shared.b16 {%0,%1,%2,%3}, [%4];"
                 : "=r"(r0), "=r"(r1), "=r"(r2), "=r"(r3) : "r"(addr));
}
__device__ __forceinline__ void mma_bf16(float& c0, float& c1, float& c2, float& c3,
                                         uint32_t a0, uint32_t a1, uint32_t a2, uint32_t a3,
                                         uint32_t b0, uint32_t b1) {
    asm volatile("mma.sync.aligned.m16n8k16.row.col.f32.bf16.bf16.f32 "
                 "{%0,%1,%2,%3}, {%4,%5,%6,%7}, {%8,%9}, {%0,%1,%2,%3};"
                 : "+f"(c0), "+f"(c1), "+f"(c2), "+f"(c3)
                 : "r"(a0), "r"(a1), "r"(a2), "r"(a3), "r"(b0), "r"(b1));
}
__device__ __forceinline__ float ex2f(float x) {
    float r; asm("ex2.approx.f32 %0, %1;" : "=f"(r) : "f"(x)); return r;
}
__device__ __forceinline__ unsigned long long packf2(float lo, float hi) {
    unsigned long long r;
    asm("mov.b64 %0, {%1, %2};" : "=l"(r) : "f"(lo), "f"(hi));
    return r;
}
__device__ __forceinline__ void unpackf2(unsigned long long v, float& lo, float& hi) {
    asm("mov.b64 {%0, %1}, %2;" : "=f"(lo), "=f"(hi) : "l"(v));
}
__device__ __forceinline__ void fma2acc(unsigned long long& acc, unsigned long long a,
                                        unsigned long long b) {
    asm("fma.rn.f32x2 %0, %1, %2, %0;" : "+l"(acc) : "l"(a), "l"(b));
}
__device__ __forceinline__ void add2acc(unsigned long long& acc, unsigned long long a) {
    asm("add.rn.f32x2 %0, %1, %2;" : "=l"(acc) : "l"(a), "l"(acc));
}

// ---------------- fused tile kernel ----------------
// One CTA (128 thr) = one full 128x128 triangular tile. A loaded once (32KB).
// B streamed as four 32-col slices (8KB) with a 2-buffer cp.async pipeline.
// Diagonal tiles alias B slices into the A tile (no B traffic at all).
__global__ __launch_bounds__(128, 4)
void tile_kernel() {
    const int L = blockIdx.x;
    int I = (int)floorf((2.0f * NT + 1.0f
                         - sqrtf((2.0f * NT + 1.0f) * (2.0f * NT + 1.0f) - 8.0f * (float)L))
                        * 0.5f);
    while (I * NT - I * (I - 1) / 2 > L) --I;
    while ((I + 1) * NT - (I + 1) * I / 2 <= L) ++I;
    const int J = I + (L - (I * NT - I * (I - 1) / 2));

    const bool diagT = (I == J);
    const bool posT  = (J == I + POS_DELTA);

    extern __shared__ unsigned char smem[];
    uint4* sA4   = reinterpret_cast<uint4*>(smem);             // 32KB: 128 rows x 256B
    uint4* sB4_0 = reinterpret_cast<uint4*>(smem + 32768);     // 8KB slice buf 0
    uint4* sB4_1 = reinterpret_cast<uint4*>(smem + 40960);     // 8KB slice buf 1
    float* redCol = reinterpret_cast<float*>(smem + 49152);    // [128]
    float* redS   = reinterpret_cast<float*>(smem + 49664);    // [2]: s2, pos

    const int t = threadIdx.x, wid = t >> 5, lane = t & 31;
    const uint32_t sAa  = smem_u32(sA4);
    const uint32_t sB0a = smem_u32(sB4_0);
    const uint32_t sB1a = smem_u32(sB4_1);

    // initial loads: A tile (+ B slice 0 if off-diagonal), one group
    {
        const uint4* srcA = g_bf16 + I * 2048;
#pragma unroll
        for (int i = 0; i < 16; ++i)
            cp_async16(sAa + (i * 128 + t) * 16, srcA + i * 128 + t);
        if (!diagT) {
            const uint4* srcB = g_bf16 + J * 2048;           // rows 0..31 = 512 uint4
#pragma unroll
            for (int i = 0; i < 4; ++i)
                cp_async16(sB0a + (i * 128 + t) * 16, srcB + i * 128 + t);
        }
        cp_commit();
    }
    if (t < 128) redCol[t] = 0.f;
    if (t < 2) redS[t] = 0.f;

    // ldmatrix lane addressing
    const int aRow0 = wid * 32 + (lane & 15);
    const int aSub  = lane >> 4;
    const int bRowB = (lane & 7) + ((lane >> 4) << 3);        // rows 0..15 of slice
    const int bSub  = (lane >> 3) & 1;

    const int groupID = lane >> 2, qp = lane & 3;
    float pos = 0.f;
    unsigned long long s2p = 0ull;
    unsigned long long rAcc[2][2] = {{0ull, 0ull}, {0ull, 0ull}};   // persists across slices

#pragma unroll
    for (int s = 0; s < 4; ++s) {
        cp_wait_all();
        __syncthreads();          // slice s resident; all warps done with slice s-1

        // prefetch slice s+1 into the other buffer (overlaps this slice's compute)
        if (s < 3 && !diagT) {
            const uint4* srcB = g_bf16 + J * 2048 + (s + 1) * 512;
            uint32_t dst = ((s + 1) & 1) ? sB1a : sB0a;
#pragma unroll
            for (int i = 0; i < 4; ++i)
                cp_async16(dst + (i * 128 + t) * 16, srcB + i * 128 + t);
        }
        cp_commit();

        const uint32_t sBa = diagT ? (sAa + s * 8192) : ((s & 1) ? sB1a : sB0a);

        float acc[2][4][4];
#pragma unroll
        for (int mi = 0; mi < 2; ++mi)
#pragma unroll
            for (int ni = 0; ni < 4; ++ni)
#pragma unroll
                for (int k = 0; k < 4; ++k) acc[mi][ni][k] = 0.f;

#pragma unroll
        for (int kc = 0; kc < 8; ++kc) {
            uint32_t a[2][4];
#pragma unroll
            for (int mi = 0; mi < 2; ++mi) {
                int row = aRow0 + mi * 16;
                uint32_t addr = sAa + row * 256 + (((2 * kc + aSub) ^ (row & 7)) << 4);
                ldmatrix_x4(a[mi][0], a[mi][1], a[mi][2], a[mi][3], addr);
            }
            uint32_t b[4][2];
#pragma unroll
            for (int p = 0; p < 2; ++p) {
                int row = bRowB + p * 16;   // slice-local; (row&7) invariant to 32-row offset
                uint32_t addr = sBa + row * 256 + (((2 * kc + bSub) ^ (row & 7)) << 4);
                uint32_t r0, r1, r2, r3;
                ldmatrix_x4(r0, r1, r2, r3, addr);
                b[2 * p][0] = r0; b[2 * p][1] = r1;
                b[2 * p + 1][0] = r2; b[2 * p + 1][1] = r3;
            }
#pragma unroll
            for (int mi = 0; mi < 2; ++mi)
#pragma unroll
                for (int ni = 0; ni < 4; ++ni)
                    mma_bf16(acc[mi][ni][0], acc[mi][ni][1], acc[mi][ni][2], acc[mi][ni][3],
                             a[mi][0], a[mi][1], a[mi][2], a[mi][3], b[ni][0], b[ni][1]);
        }

        // ---- epilogue for this 128x32 slice
        unsigned long long cAcc[4] = {0ull, 0ull, 0ull, 0ull};
        const bool special = diagT || posT;
#pragma unroll
        for (int mi = 0; mi < 2; ++mi) {
            const int r0 = wid * 32 + mi * 16 + groupID;
            const int r1 = r0 + 8;
#pragma unroll
            for (int ni = 0; ni < 4; ++ni) {
                float e00 = ex2f(fmaf(acc[mi][ni][0], LOG2E, -LOG2E));
                float e01 = ex2f(fmaf(acc[mi][ni][1], LOG2E, -LOG2E));
                float e10 = ex2f(fmaf(acc[mi][ni][2], LOG2E, -LOG2E));
                float e11 = ex2f(fmaf(acc[mi][ni][3], LOG2E, -LOG2E));
                if (special) {
                    e00 = fminf(e00, 1.0f); e01 = fminf(e01, 1.0f);
                    e10 = fminf(e10, 1.0f); e11 = fminf(e11, 1.0f);
                    const int g0 = s * 32 + ni * 8 + 2 * qp, g1 = g0 + 1;
                    if (diagT) {
                        if (r0 == g0) e00 = 1.0f;
                        if (r0 == g1) e01 = 1.0f;
                        if (r1 == g0) e10 = 1.0f;
                        if (r1 == g1) e11 = 1.0f;
                    }
                    if (posT) {
                        if (r0 == g0) pos += e00;
                        if (r0 == g1) pos += e01;
                        if (r1 == g0) pos += e10;
                        if (r1 == g1) pos += e11;
                    }
                }
                unsigned long long p0 = packf2(e00, e01);
                unsigned long long p1 = packf2(e10, e11);
                fma2acc(s2p, p0, p0);
                fma2acc(s2p, p1, p1);
                add2acc(rAcc[mi][0], p0);
                add2acc(rAcc[mi][1], p1);
                add2acc(cAcc[ni], p0);
                add2acc(cAcc[ni], p1);
            }
        }
        // column partials for this slice -> smem
#pragma unroll
        for (int ni = 0; ni < 4; ++ni) {
            float lo, hi; unpackf2(cAcc[ni], lo, hi);
#pragma unroll
            for (int o = 4; o < 32; o <<= 1) {
                lo += __shfl_xor_sync(0xffffffffu, lo, o);
                hi += __shfl_xor_sync(0xffffffffu, hi, o);
            }
            if (lane < 4) {
                atomicAdd(&redCol[s * 32 + ni * 8 + 2 * qp], lo);
                atomicAdd(&redCol[s * 32 + ni * 8 + 2 * qp + 1], hi);
            }
        }
    }

    // ---- row sums: each row owned by one (wid, mi, h, groupID)
#pragma unroll
    for (int mi = 0; mi < 2; ++mi)
#pragma unroll
        for (int h = 0; h < 2; ++h) {
            float lo, hi; unpackf2(rAcc[mi][h], lo, hi);
            float v = lo + hi;
            v += __shfl_xor_sync(0xffffffffu, v, 1);
            v += __shfl_xor_sync(0xffffffffu, v, 2);
            if (qp == 0)
                atomicAdd(&g_rowsum[I * BT + wid * 32 + mi * 16 + h * 8 + groupID],
                          (double)v);
        }
    // scalars
    {
        float lo, hi; unpackf2(s2p, lo, hi);
        float s2 = lo + hi;
#pragma unroll
        for (int o = 16; o; o >>= 1) {
            s2 += __shfl_xor_sync(0xffffffffu, s2, o);
            pos += __shfl_xor_sync(0xffffffffu, pos, o);
        }
        if (lane == 0) {
            atomicAdd(&redS[0], s2);
            if (posT) atomicAdd(&redS[1], pos);
        }
    }
    __syncthreads();

    if (t == 0) {
        double w = diagT ? 1.0 : 2.0;
        atomicAdd(&g_S2, w * (double)redS[0]);
        if (posT) atomicAdd(&g_POS, 2.0 * (double)redS[1]);
    }
    if (!diagT)
        atomicAdd(&g_rowsum[J * BT + t], (double)redCol[t]);
}

// ---------------- rowsum partial reduction (64 CTAs) ----------------
__global__ void reduce_kernel() {
    __shared__ double sh1[256];
    __shared__ double sh2[256];
    int t = threadIdx.x;
    int base = blockIdx.x * 128;
    double sr1 = 0.0, sr2 = 0.0;
    if (t < 128) {
        double rv = g_rowsum[base + t];
        sr1 = rv; sr2 = rv * rv;
    }
    sh1[t] = sr1; sh2[t] = sr2;
    __syncthreads();
    for (int s = 64; s; s >>= 1) {
        if (t < s) { sh1[t] += sh1[t + s]; sh2[t] += sh2[t + s]; }
        __syncthreads();
    }
    if (t == 0) { atomicAdd(&g_R1, sh1[0]); atomicAdd(&g_R2, sh2[0]); }
}

// ---------------- final combine ----------------
__global__ void final_kernel(float* out) {
    const double Nd = (double)NROWS, Bd = (double)BHALF;
    double S1 = g_R1;
    double S2 = g_S2, POS = g_POS, SR2 = g_R2;
    double trace = Nd;                        // K_ii == 1 exactly
    double neg   = S1 - trace - POS;
    double term1 = POS / (Bd * 2.0);          // B*M*(M-1), M=2
    double term2 = neg / (Bd * Bd * 4.0);     // B^2*M^2
    double scale = Bd / (Bd - 1.0);
    double hsic_zy = scale * (term1 - term2 - 1.0);
    double hsic_zz = (S2 - 2.0 * SR2 / Nd + (S1 / Nd) * (S1 / Nd)) / (Nd * Nd);
    if (hsic_zz < 0.0) hsic_zz = 0.0;
    out[0] = (float)(-hsic_zy + 3.0 * sqrt(hsic_zz));
}

extern "C" void kernel_launch(void* const* d_in, const int* in_sizes, int n_in,
                              void* d_out, int out_size) {
    const float* feat = (const float*)d_in[0];
    float* out = (float*)d_out;

    const int tile_smem = 49672;   // 32K A + 16K B bufs + redCol + redS
    cudaFuncSetAttribute(tile_kernel, cudaFuncAttributeMaxDynamicSharedMemorySize, tile_smem);

    prep_kernel<<<(NROWS * 16) / 128, 128>>>(feat);
    tile_kernel<<<NTILES, 128, tile_smem>>>();
    reduce_kernel<<<NT, 256>>>();
    final_kernel<<<1, 1>>>(out);
}

// round 8
// speedup vs baseline: 9.8058x; 1.0477x over previous
#include <cuda_runtime.h>
#include <cuda_bf16.h>
#include <math.h>
#include <stdint.h>

#define NROWS 8192
#define DIM   128
#define BHALF 4096
#define BT    128
#define NT    (NROWS / BT)          // 64
#define NTILES (NT * (NT + 1) / 2)  // 2080
#define POS_DELTA (BHALF / BT)      // 32
#define LOG2E 1.4426950408889634f

// ---------------- global scratch (no allocations allowed) ----------------
__device__ double g_S2, g_POS, g_R1, g_R2;
__device__ unsigned g_ticket;
__device__ double g_rowsum[NROWS];
__device__ __align__(16) uint4 g_bf16[NROWS * 16];      // pre-swizzled bf16 rows (256B/row)

// ---------------- prep: init + bf16 convert (norms == 0.5 exactly: l2-normalized)
__global__ void prep_kernel(const float* __restrict__ feat) {
    int t = blockIdx.x * blockDim.x + threadIdx.x;   // one uint4 (8 bf16) per thread
    int row = t >> 4;
    int chunk = t & 15;
    const float4* src = reinterpret_cast<const float4*>(feat + row * DIM + chunk * 8);
    float4 a = src[0], b = src[1];
    if (chunk == 0) g_rowsum[row] = 0.0;
    if (t == 0) { g_S2 = 0.0; g_POS = 0.0; g_R1 = 0.0; g_R2 = 0.0; g_ticket = 0u; }

    __nv_bfloat162 p0 = __floats2bfloat162_rn(a.x, a.y);
    __nv_bfloat162 p1 = __floats2bfloat162_rn(a.z, a.w);
    __nv_bfloat162 p2 = __floats2bfloat162_rn(b.x, b.y);
    __nv_bfloat162 p3 = __floats2bfloat162_rn(b.z, b.w);
    uint4 v;
    v.x = *reinterpret_cast<uint32_t*>(&p0);
    v.y = *reinterpret_cast<uint32_t*>(&p1);
    v.z = *reinterpret_cast<uint32_t*>(&p2);
    v.w = *reinterpret_cast<uint32_t*>(&p3);
    g_bf16[row * 16 + (chunk ^ (row & 7))] = v;   // 16B-granular XOR swizzle
}

// ---------------- helpers ----------------
__device__ __forceinline__ uint32_t smem_u32(const void* p) {
    uint32_t a;
    asm("{ .reg .u64 t; cvta.to.shared.u64 t, %1; cvt.u32.u64 %0, t; }" : "=r"(a) : "l"(p));
    return a;
}
__device__ __forceinline__ void cp_async16(uint32_t saddr, const void* gaddr) {
    asm volatile("cp.async.cg.shared.global [%0], [%1], 16;" :: "r"(saddr), "l"(gaddr));
}
__device__ __forceinline__ void cp_commit() {
    asm volatile("cp.async.commit_group;" ::: "memory");
}
__device__ __forceinline__ void cp_wait_all() {
    asm volatile("cp.async.wait_group 0;" ::: "memory");
}
template<int N>
__device__ __forceinline__ void cp_wait() {
    asm volatile("cp.async.wait_group %0;" :: "n"(N) : "memory");
}
__device__ __forceinline__ void ldmatrix_x4(uint32_t& r0, uint32_t& r1, uint32_t& r2,
                                            uint32_t& r3, uint32_t addr) {
    asm volatile("ldmatrix.sync.aligned.m8n8.x4.shared.b16 {%0,%1,%2,%3}, [%4];"
                 : "=r"(r0), "=r"(r1), "=r"(r2), "=r"(r3) : "r"(addr));
}
__device__ __forceinline__ void mma_bf16(float& c0, float& c1, float& c2, float& c3,
                                         uint32_t a0, uint32_t a1, uint32_t a2, uint32_t a3,
                                         uint32_t b0, uint32_t b1) {
    asm volatile("mma.sync.aligned.m16n8k16.row.col.f32.bf16.bf16.f32 "
                 "{%0,%1,%2,%3}, {%4,%5,%6,%7}, {%8,%9}, {%0,%1,%2,%3};"
                 : "+f"(c0), "+f"(c1), "+f"(c2), "+f"(c3)
                 : "r"(a0), "r"(a1), "r"(a2), "r"(a3), "r"(b0), "r"(b1));
}
__device__ __forceinline__ float ex2f(float x) {
    float r; asm("ex2.approx.f32 %0, %1;" : "=f"(r) : "f"(x)); return r;
}
__device__ __forceinline__ unsigned long long packf2(float lo, float hi) {
    unsigned long long r;
    asm("mov.b64 %0, {%1, %2};" : "=l"(r) : "f"(lo), "f"(hi));
    return r;
}
__device__ __forceinline__ void unpackf2(unsigned long long v, float& lo, float& hi) {
    asm("mov.b64 {%0, %1}, %2;" : "=f"(lo), "=f"(hi) : "l"(v));
}
__device__ __forceinline__ void fma2acc(unsigned long long& acc, unsigned long long a,
                                        unsigned long long b) {
    asm("fma.rn.f32x2 %0, %1, %2, %0;" : "+l"(acc) : "l"(a), "l"(b));
}
__device__ __forceinline__ void add2acc(unsigned long long& acc, unsigned long long a) {
    asm("add.rn.f32x2 %0, %1, %2;" : "=l"(acc) : "l"(a), "l"(acc));
}

// ---------------- fused tile kernel ----------------
// One CTA (128 thr, 4 warps) = one 128x128 triangular tile.
// A is loaded once and hoisted into register fragments (64 regs/thread);
// B streamed as four 32-col slices through a 2-buffer cp.async pipeline.
__global__ __launch_bounds__(128, 4)
void tile_kernel() {
    const int L = blockIdx.x;
    int I = (int)floorf((2.0f * NT + 1.0f
                         - sqrtf((2.0f * NT + 1.0f) * (2.0f * NT + 1.0f) - 8.0f * (float)L))
                        * 0.5f);
    while (I * NT - I * (I - 1) / 2 > L) --I;
    while ((I + 1) * NT - (I + 1) * I / 2 <= L) ++I;
    const int J = I + (L - (I * NT - I * (I - 1) / 2));

    const bool diagT = (I == J);
    const bool posT  = (J == I + POS_DELTA);

    extern __shared__ unsigned char smem[];
    // stage: 32KB for A load, then reused as two 8KB B slice buffers
    float* redRow = reinterpret_cast<float*>(smem + 32768);    // [128]
    float* redCol = reinterpret_cast<float*>(smem + 33280);    // [128]
    float* redS   = reinterpret_cast<float*>(smem + 33792);    // [2]: s2, pos

    const int t = threadIdx.x, wid = t >> 5, lane = t & 31;
    const uint32_t stg = smem_u32(smem);

    // ---- load A tile into stage, extract register fragments
    {
        const uint4* srcA = g_bf16 + I * 2048;
#pragma unroll
        for (int i = 0; i < 16; ++i)
            cp_async16(stg + (i * 128 + t) * 16, srcA + i * 128 + t);
        cp_commit();
    }
    if (t < 128) { redRow[t] = 0.f; redCol[t] = 0.f; }
    if (t < 2) redS[t] = 0.f;
    cp_wait_all();
    __syncthreads();

    const int aRow0 = wid * 32 + (lane & 15);
    const int aSub  = lane >> 4;
    uint32_t aF[8][2][4];                     // [kc][mi][frag]: 64 regs
#pragma unroll
    for (int kc = 0; kc < 8; ++kc)
#pragma unroll
        for (int mi = 0; mi < 2; ++mi) {
            int row = aRow0 + mi * 16;
            uint32_t addr = stg + row * 256 + (((2 * kc + aSub) ^ (row & 7)) << 4);
            ldmatrix_x4(aF[kc][mi][0], aF[kc][mi][1], aF[kc][mi][2], aF[kc][mi][3], addr);
        }
    __syncthreads();      // all warps done reading A before stage is reused for B

    // ---- B pipeline: slice 0 into buf0, prefetch-1 ahead
    {
        const uint4* srcB = g_bf16 + J * 2048;
#pragma unroll
        for (int i = 0; i < 4; ++i)
            cp_async16(stg + (i * 128 + t) * 16, srcB + i * 128 + t);
        cp_commit();
    }

    const int bRowB = (lane & 7) + ((lane >> 4) << 3);
    const int bSub  = (lane >> 3) & 1;
    const int groupID = lane >> 2, qp = lane & 3;

    float pos = 0.f;
    unsigned long long s2p = 0ull;
    unsigned long long rAcc[2][2] = {{0ull, 0ull}, {0ull, 0ull}};

#pragma unroll
    for (int s = 0; s < 4; ++s) {
        cp_wait_all();
        __syncthreads();

        if (s < 3) {
            const uint4* srcB = g_bf16 + J * 2048 + (s + 1) * 512;
            uint32_t dst = stg + (((s + 1) & 1) ? 8192 : 0);
#pragma unroll
            for (int i = 0; i < 4; ++i)
                cp_async16(dst + (i * 128 + t) * 16, srcB + i * 128 + t);
        }
        cp_commit();

        const uint32_t sBa = stg + ((s & 1) ? 8192 : 0);

        float acc[2][4][4];
#pragma unroll
        for (int mi = 0; mi < 2; ++mi)
#pragma unroll
            for (int ni = 0; ni < 4; ++ni)
#pragma unroll
                for (int k = 0; k < 4; ++k) acc[mi][ni][k] = 0.f;

#pragma unroll
        for (int kc = 0; kc < 8; ++kc) {
            uint32_t b[4][2];
#pragma unroll
            for (int p = 0; p < 2; ++p) {
                int row = bRowB + p * 16;
                uint32_t addr = sBa + row * 256 + (((2 * kc + bSub) ^ (row & 7)) << 4);
                uint32_t r0, r1, r2, r3;
                ldmatrix_x4(r0, r1, r2, r3, addr);
                b[2 * p][0] = r0; b[2 * p][1] = r1;
                b[2 * p + 1][0] = r2; b[2 * p + 1][1] = r3;
            }
#pragma unroll
            for (int mi = 0; mi < 2; ++mi)
#pragma unroll
                for (int ni = 0; ni < 4; ++ni)
                    mma_bf16(acc[mi][ni][0], acc[mi][ni][1], acc[mi][ni][2], acc[mi][ni][3],
                             aF[kc][mi][0], aF[kc][mi][1], aF[kc][mi][2], aF[kc][mi][3],
                             b[ni][0], b[ni][1]);
        }

        // ---- epilogue for this 128x32 slice
        unsigned long long cAcc[4] = {0ull, 0ull, 0ull, 0ull};
        const bool special = diagT || posT;
#pragma unroll
        for (int mi = 0; mi < 2; ++mi) {
            const int r0 = wid * 32 + mi * 16 + groupID;
            const int r1 = r0 + 8;
#pragma unroll
            for (int ni = 0; ni < 4; ++ni) {
                float e00 = ex2f(fmaf(acc[mi][ni][0], LOG2E, -LOG2E));
                float e01 = ex2f(fmaf(acc[mi][ni][1], LOG2E, -LOG2E));
                float e10 = ex2f(fmaf(acc[mi][ni][2], LOG2E, -LOG2E));
                float e11 = ex2f(fmaf(acc[mi][ni][3], LOG2E, -LOG2E));
                if (special) {
                    e00 = fminf(e00, 1.0f); e01 = fminf(e01, 1.0f);
                    e10 = fminf(e10, 1.0f); e11 = fminf(e11, 1.0f);
                    const int g0 = s * 32 + ni * 8 + 2 * qp, g1 = g0 + 1;
                    if (diagT) {
                        if (r0 == g0) e00 = 1.0f;
                        if (r0 == g1) e01 = 1.0f;
                        if (r1 == g0) e10 = 1.0f;
                        if (r1 == g1) e11 = 1.0f;
                    }
                    if (posT) {
                        if (r0 == g0) pos += e00;
                        if (r0 == g1) pos += e01;
                        if (r1 == g0) pos += e10;
                        if (r1 == g1) pos += e11;
                    }
                }
                unsigned long long p0 = packf2(e00, e01);
                unsigned long long p1 = packf2(e10, e11);
                fma2acc(s2p, p0, p0);
                fma2acc(s2p, p1, p1);
                add2acc(rAcc[mi][0], p0);
                add2acc(rAcc[mi][1], p1);
                add2acc(cAcc[ni], p0);
                add2acc(cAcc[ni], p1);
            }
        }
#pragma unroll
        for (int ni = 0; ni < 4; ++ni) {
            float lo, hi; unpackf2(cAcc[ni], lo, hi);
#pragma unroll
            for (int o = 4; o < 32; o <<= 1) {
                lo += __shfl_xor_sync(0xffffffffu, lo, o);
                hi += __shfl_xor_sync(0xffffffffu, hi, o);
            }
            if (lane < 4) {
                atomicAdd(&redCol[s * 32 + ni * 8 + 2 * qp], lo);
                atomicAdd(&redCol[s * 32 + ni * 8 + 2 * qp + 1], hi);
            }
        }
    }

    // ---- row sums: each row owned by one (wid, mi, h, groupID) -> plain store
#pragma unroll
    for (int mi = 0; mi < 2; ++mi)
#pragma unroll
        for (int h = 0; h < 2; ++h) {
            float lo, hi; unpackf2(rAcc[mi][h], lo, hi);
            float v = lo + hi;
            v += __shfl_xor_sync(0xffffffffu, v, 1);
            v += __shfl_xor_sync(0xffffffffu, v, 2);
            if (qp == 0) redRow[wid * 32 + mi * 16 + h * 8 + groupID] = v;
        }
    // scalars
    {
        float lo, hi; unpackf2(s2p, lo, hi);
        float s2 = lo + hi;
#pragma unroll
        for (int o = 16; o; o >>= 1) {
            s2 += __shfl_xor_sync(0xffffffffu, s2, o);
            pos += __shfl_xor_sync(0xffffffffu, pos, o);
        }
        if (lane == 0) {
            atomicAdd(&redS[0], s2);
            if (posT) atomicAdd(&redS[1], pos);
        }
    }
    __syncthreads();

    if (t == 0) {
        double w = diagT ? 1.0 : 2.0;
        atomicAdd(&g_S2, w * (double)redS[0]);
        if (posT) atomicAdd(&g_POS, 2.0 * (double)redS[1]);
    }
    atomicAdd(&g_rowsum[I * BT + t], (double)redRow[t]);
    if (!diagT)
        atomicAdd(&g_rowsum[J * BT + t], (double)redCol[t]);
}

// ---------------- fused rowsum reduction + final combine (ticketed) --------
__global__ void reduce_final_kernel(float* out) {
    const int t = threadIdx.x, wid = t >> 5, lane = t & 31;
    double rv = g_rowsum[blockIdx.x * 128 + t];
    double s1 = rv, s2v = rv * rv;
#pragma unroll
    for (int o = 16; o; o >>= 1) {
        s1  += __shfl_xor_sync(0xffffffffu, s1, o);
        s2v += __shfl_xor_sync(0xffffffffu, s2v, o);
    }
    __shared__ double w1[4], w2[4];
    if (lane == 0) { w1[wid] = s1; w2[wid] = s2v; }
    __syncthreads();
    if (t == 0) {
        atomicAdd(&g_R1, w1[0] + w1[1] + w1[2] + w1[3]);
        atomicAdd(&g_R2, w2[0] + w2[1] + w2[2] + w2[3]);
        __threadfence();
        unsigned tk = atomicAdd(&g_ticket, 1u);
        if (tk == NT - 1) {                     // last CTA: combine
            const double Nd = (double)NROWS, Bd = (double)BHALF;
            double S1 = g_R1, S2 = g_S2, POS = g_POS, SR2 = g_R2;
            double trace = Nd;                  // K_ii == 1 exactly
            double neg   = S1 - trace - POS;
            double term1 = POS / (Bd * 2.0);    // B*M*(M-1), M=2
            double term2 = neg / (Bd * Bd * 4.0);
            double scale = Bd / (Bd - 1.0);
            double hsic_zy = scale * (term1 - term2 - 1.0);
            double hsic_zz = (S2 - 2.0 * SR2 / Nd + (S1 / Nd) * (S1 / Nd)) / (Nd * Nd);
            if (hsic_zz < 0.0) hsic_zz = 0.0;
            out[0] = (float)(-hsic_zy + 3.0 * sqrt(hsic_zz));
        }
    }
}

extern "C" void kernel_launch(void* const* d_in, const int* in_sizes, int n_in,
                              void* d_out, int out_size) {
    const float* feat = (const float*)d_in[0];
    float* out = (float*)d_out;

    const int tile_smem = 33800;   // 32K stage/B bufs + redRow + redCol + redS
    cudaFuncSetAttribute(tile_kernel, cudaFuncAttributeMaxDynamicSharedMemorySize, tile_smem);

    prep_kernel<<<(NROWS * 16) / 128, 128>>>(feat);
    tile_kernel<<<NTILES, 128, tile_smem>>>();
    reduce_final_kernel<<<NT, 128>>>(out);
}